// round 2
// baseline (speedup 1.0000x reference)
#include <cuda_runtime.h>
#include <cuda_bf16.h>
#include <math.h>

// Problem constants
#define SEQ   2048
#define HID   4096
#define NH    32
#define NKV   8
#define DH    128
#define QDIM  (NH * DH)    // 4096
#define KVDIM (NKV * DH)   // 1024

// Scratch (device globals; allocation is forbidden)
__device__ float g_q [SEQ * QDIM];
__device__ float g_k [SEQ * KVDIM];
__device__ float g_v [SEQ * KVDIM];
__device__ float g_ao[SEQ * QDIM];

// ---------------------------------------------------------------------------
// SGEMM: C[M,N] = A[M,K] @ B[N,K]^T    (A,B,C row-major)
// 128x128 tile, BK=8, 256 threads, 8x8 microtile
// ---------------------------------------------------------------------------
__global__ __launch_bounds__(256) void sgemm_tn(
    const float* __restrict__ A, const float* __restrict__ B,
    float* __restrict__ C, int M, int N, int K)
{
    __shared__ float As[8][128];
    __shared__ float Bs[8][128];

    const int tid  = threadIdx.x;
    const int bm   = blockIdx.y * 128;
    const int bn   = blockIdx.x * 128;
    const int lrow = tid >> 1;          // 0..127
    const int lcol = (tid & 1) << 2;    // 0 or 4
    const int tx   = tid & 15;
    const int ty   = tid >> 4;

    const float* Ap = A + (bm + lrow) * K + lcol;
    const float* Bp = B + (bn + lrow) * K + lcol;

    float acc[8][8];
    #pragma unroll
    for (int i = 0; i < 8; i++)
        #pragma unroll
        for (int j = 0; j < 8; j++) acc[i][j] = 0.f;

    for (int k0 = 0; k0 < K; k0 += 8) {
        float4 a4 = *(const float4*)(Ap + k0);
        float4 b4 = *(const float4*)(Bp + k0);
        As[lcol+0][lrow] = a4.x; As[lcol+1][lrow] = a4.y;
        As[lcol+2][lrow] = a4.z; As[lcol+3][lrow] = a4.w;
        Bs[lcol+0][lrow] = b4.x; Bs[lcol+1][lrow] = b4.y;
        Bs[lcol+2][lrow] = b4.z; Bs[lcol+3][lrow] = b4.w;
        __syncthreads();

        #pragma unroll
        for (int kk = 0; kk < 8; kk++) {
            float ar[8], br[8];
            *(float4*)(ar)   = *(const float4*)&As[kk][ty*8];
            *(float4*)(ar+4) = *(const float4*)&As[kk][ty*8+4];
            *(float4*)(br)   = *(const float4*)&Bs[kk][tx*8];
            *(float4*)(br+4) = *(const float4*)&Bs[kk][tx*8+4];
            #pragma unroll
            for (int i = 0; i < 8; i++)
                #pragma unroll
                for (int j = 0; j < 8; j++)
                    acc[i][j] = fmaf(ar[i], br[j], acc[i][j]);
        }
        __syncthreads();
    }

    float* Cp = C + (bm + ty*8) * N + bn + tx*8;
    #pragma unroll
    for (int i = 0; i < 8; i++) {
        *(float4*)(Cp + i*N)     = make_float4(acc[i][0], acc[i][1], acc[i][2], acc[i][3]);
        *(float4*)(Cp + i*N + 4) = make_float4(acc[i][4], acc[i][5], acc[i][6], acc[i][7]);
    }
}

// ---------------------------------------------------------------------------
// RoPE (in-place), optional scale folded in (1/sqrt(D) for Q)
// X: [SEQ, nheads*DH]; cos/sin: [SEQ,128] with cos[d]==cos[d+64]
// ---------------------------------------------------------------------------
__global__ void rope_kernel(float* __restrict__ X,
                            const float* __restrict__ cosb,
                            const float* __restrict__ sinb,
                            int nheads, float scale)
{
    int idx = blockIdx.x * blockDim.x + threadIdx.x;
    int total = SEQ * nheads * 64;
    if (idx >= total) return;
    int d = idx & 63;
    int h = (idx >> 6) % nheads;
    int s = idx / (nheads * 64);
    float c  = cosb[s * 128 + d];
    float sn = sinb[s * 128 + d];
    float* p = X + (size_t)s * nheads * DH + h * DH;
    float x0 = p[d], x1 = p[d + 64];
    p[d]      = (x0 * c - x1 * sn) * scale;
    p[d + 64] = (x1 * c + x0 * sn) * scale;
}

// ---------------------------------------------------------------------------
// Flash attention, fp32, causal, GQA (kv head = qhead >> 2).
// Q pre-scaled by 1/sqrt(D). Tiles: 64 q-rows x 64 kv-cols, 256 threads.
// Smem: QsT[128][64], KsT[128][64], Vs[64][128], Ss[64][65], m/l/corr[64]
// ---------------------------------------------------------------------------
#define FBR 64
#define FBC 64
#define SS_STRIDE 65
#define FLASH_SMEM ((128*64*2 + 64*128 + 64*SS_STRIDE + 3*64) * 4)

__global__ __launch_bounds__(256) void flash_attn(
    const float* __restrict__ Q, const float* __restrict__ K,
    const float* __restrict__ V, float* __restrict__ O)
{
    extern __shared__ float sm[];
    float* QsT = sm;                 // [128][64]  (d-major)
    float* KsT = QsT + 128*64;       // [128][64]
    float* Vs  = KsT + 128*64;       // [64][128]
    float* Ss  = Vs  + 64*128;       // [64][65]
    float* ms  = Ss  + 64*SS_STRIDE;
    float* ls  = ms + 64;
    float* cr  = ls + 64;

    const int tid = threadIdx.x;
    const int qt  = blockIdx.x;      // q tile index
    const int h   = blockIdx.y;      // q head
    const int kvh = h >> 2;
    const int q0  = qt * FBR;
    const int tx  = tid & 15;
    const int ty  = tid >> 4;
    const int orow = tid & 63;       // PV: row owned
    const int och  = tid >> 6;       // PV: 32-col chunk owned

    // Load Q tile transposed: QsT[d][r]
    for (int idx = tid; idx < 64 * 32; idx += 256) {
        int r = idx & 63, d4 = idx >> 6;
        float4 v = *(const float4*)(Q + (size_t)(q0 + r) * QDIM + h * DH + d4 * 4);
        QsT[(d4*4+0)*64 + r] = v.x;
        QsT[(d4*4+1)*64 + r] = v.y;
        QsT[(d4*4+2)*64 + r] = v.z;
        QsT[(d4*4+3)*64 + r] = v.w;
    }
    if (tid < 64) { ms[tid] = -1e30f; ls[tid] = 0.f; }

    float acc[32];
    #pragma unroll
    for (int i = 0; i < 32; i++) acc[i] = 0.f;

    for (int kt = 0; kt <= qt; kt++) {
        const int k0 = kt * FBC;

        // Load K tile transposed: KsT[d][c]
        for (int idx = tid; idx < 64 * 32; idx += 256) {
            int c = idx & 63, d4 = idx >> 6;
            float4 v = *(const float4*)(K + (size_t)(k0 + c) * KVDIM + kvh * DH + d4 * 4);
            KsT[(d4*4+0)*64 + c] = v.x;
            KsT[(d4*4+1)*64 + c] = v.y;
            KsT[(d4*4+2)*64 + c] = v.z;
            KsT[(d4*4+3)*64 + c] = v.w;
        }
        __syncthreads();   // Q/K tiles ready; prior PV done (Ss safe to write)

        // Scores: S = Q @ K^T  (4x4 microtile per thread)
        float s4[4][4];
        #pragma unroll
        for (int i = 0; i < 4; i++)
            #pragma unroll
            for (int j = 0; j < 4; j++) s4[i][j] = 0.f;

        #pragma unroll 8
        for (int kk = 0; kk < DH; kk++) {
            float4 qv = *(const float4*)&QsT[kk*64 + ty*4];
            float4 kv = *(const float4*)&KsT[kk*64 + tx*4];
            float qa[4] = {qv.x, qv.y, qv.z, qv.w};
            float ka[4] = {kv.x, kv.y, kv.z, kv.w};
            #pragma unroll
            for (int i = 0; i < 4; i++)
                #pragma unroll
                for (int j = 0; j < 4; j++)
                    s4[i][j] = fmaf(qa[i], ka[j], s4[i][j]);
        }
        #pragma unroll
        for (int i = 0; i < 4; i++)
            #pragma unroll
            for (int j = 0; j < 4; j++)
                Ss[(ty*4+i)*SS_STRIDE + tx*4 + j] = s4[i][j];
        __syncthreads();   // scores complete; KsT free

        // V load (overlapped with softmax row pass)
        for (int idx = tid; idx < 64 * 32; idx += 256) {
            int c = idx >> 5, d4 = idx & 31;
            *(float4*)&Vs[c*128 + d4*4] =
                *(const float4*)(V + (size_t)(k0 + c) * KVDIM + kvh * DH + d4 * 4);
        }
        if (tid < 64) {
            int r = tid;
            int lim = (kt == qt) ? (r + 1) : FBC;   // causal
            float mold = ms[r];
            float m = mold;
            for (int c = 0; c < lim; c++) m = fmaxf(m, Ss[r*SS_STRIDE + c]);
            float corr = __expf(mold - m);
            float l = ls[r] * corr;
            for (int c = 0; c < FBC; c++) {
                float p = (c < lim) ? __expf(Ss[r*SS_STRIDE + c] - m) : 0.f;
                Ss[r*SS_STRIDE + c] = p;
                l += p;
            }
            ms[r] = m; ls[r] = l; cr[r] = corr;
        }
        __syncthreads();   // P and V ready

        // Rescale + PV accumulate
        float corr = cr[orow];
        #pragma unroll
        for (int i = 0; i < 32; i++) acc[i] *= corr;

        for (int c = 0; c < FBC; c++) {
            float p = Ss[orow*SS_STRIDE + c];
            const float* vrow = &Vs[c*128 + och*32];
            #pragma unroll
            for (int d4 = 0; d4 < 8; d4++) {
                float4 v = *(const float4*)(vrow + d4*4);
                acc[d4*4+0] = fmaf(p, v.x, acc[d4*4+0]);
                acc[d4*4+1] = fmaf(p, v.y, acc[d4*4+1]);
                acc[d4*4+2] = fmaf(p, v.z, acc[d4*4+2]);
                acc[d4*4+3] = fmaf(p, v.w, acc[d4*4+3]);
            }
        }
        // no sync needed: next iter's first write (KsT) is fenced by the sync
        // after the K load, which all threads must reach after finishing PV
        __syncthreads();
    }

    float inv = 1.0f / ls[orow];
    float* Op = O + (size_t)(q0 + orow) * QDIM + h * DH + och * 32;
    #pragma unroll
    for (int d4 = 0; d4 < 8; d4++) {
        float4 v = make_float4(acc[d4*4+0]*inv, acc[d4*4+1]*inv,
                               acc[d4*4+2]*inv, acc[d4*4+3]*inv);
        *(float4*)(Op + d4*4) = v;
    }
}

// ---------------------------------------------------------------------------
// Launch
// ---------------------------------------------------------------------------
extern "C" void kernel_launch(void* const* d_in, const int* in_sizes, int n_in,
                              void* d_out, int out_size)
{
    const float* hidden = (const float*)d_in[0];
    const float* cosb   = (const float*)d_in[1];
    const float* sinb   = (const float*)d_in[2];
    // d_in[3] = attention_mask (pure causal; applied analytically)
    const float* Wq     = (const float*)d_in[4];
    const float* Wk     = (const float*)d_in[5];
    const float* Wv     = (const float*)d_in[6];
    const float* Wo     = (const float*)d_in[7];
    float* out = (float*)d_out;

    float *qp, *kp, *vp, *aop;
    cudaGetSymbolAddress((void**)&qp,  g_q);
    cudaGetSymbolAddress((void**)&kp,  g_k);
    cudaGetSymbolAddress((void**)&vp,  g_v);
    cudaGetSymbolAddress((void**)&aop, g_ao);

    // Projections
    sgemm_tn<<<dim3(QDIM/128,  SEQ/128), 256>>>(hidden, Wq, qp, SEQ, QDIM,  HID);
    sgemm_tn<<<dim3(KVDIM/128, SEQ/128), 256>>>(hidden, Wk, kp, SEQ, KVDIM, HID);
    sgemm_tn<<<dim3(KVDIM/128, SEQ/128), 256>>>(hidden, Wv, vp, SEQ, KVDIM, HID);

    // RoPE (Q also gets 1/sqrt(D) folded in)
    const float scale = 0.08838834764831845f;   // 128^-0.5
    rope_kernel<<<(SEQ*NH*64 + 255)/256, 256>>>(qp, cosb, sinb, NH,  scale);
    rope_kernel<<<(SEQ*NKV*64 + 255)/256, 256>>>(kp, cosb, sinb, NKV, 1.0f);

    // Flash attention
    cudaFuncSetAttribute(flash_attn, cudaFuncAttributeMaxDynamicSharedMemorySize,
                         FLASH_SMEM);
    flash_attn<<<dim3(SEQ/FBR, NH), 256, FLASH_SMEM>>>(qp, kp, vp, aop);

    // Output projection
    sgemm_tn<<<dim3(QDIM/128, SEQ/128), 256>>>(aop, Wo, out, SEQ, QDIM, HID);
}

// round 4
// speedup vs baseline: 1.8488x; 1.8488x over previous
#include <cuda_runtime.h>
#include <cuda_bf16.h>
#include <cstdint>
#include <math.h>

// Problem constants
#define SEQ   2048
#define HID   4096
#define NH    32
#define NKV   8
#define DH    128
#define QDIM  (NH * DH)    // 4096
#define KVDIM (NKV * DH)   // 1024

// Scratch (device globals; allocation is forbidden)
__device__ float g_q [SEQ * QDIM];
__device__ float g_k [SEQ * KVDIM];
__device__ float g_v [SEQ * KVDIM];
__device__ float g_ao[SEQ * QDIM];

// ---------------------------------------------------------------------------
// Helpers: mma.sync bf16 (legacy HMMA path — compiles for plain sm_100)
// ---------------------------------------------------------------------------
__device__ __forceinline__ uint32_t smem_u32(const void* p) {
    uint32_t a;
    asm("{ .reg .u64 t; cvta.to.shared.u64 t, %1; cvt.u32.u64 %0, t; }"
        : "=r"(a) : "l"(p));
    return a;
}

#define LDM4(r, addr)                                                         \
    asm volatile("ldmatrix.sync.aligned.m8n8.x4.shared.b16 {%0,%1,%2,%3}, [%4];" \
                 : "=r"((r)[0]), "=r"((r)[1]), "=r"((r)[2]), "=r"((r)[3])     \
                 : "r"(addr))

__device__ __forceinline__ void mma_bf16(float* c, const uint32_t* a,
                                         const uint32_t* b) {
    asm volatile(
        "mma.sync.aligned.m16n8k16.row.col.f32.bf16.bf16.f32 "
        "{%0,%1,%2,%3}, {%4,%5,%6,%7}, {%8,%9}, {%0,%1,%2,%3};"
        : "+f"(c[0]), "+f"(c[1]), "+f"(c[2]), "+f"(c[3])
        : "r"(a[0]), "r"(a[1]), "r"(a[2]), "r"(a[3]), "r"(b[0]), "r"(b[1]));
}

__device__ __forceinline__ uint32_t pack_bf16x2(__nv_bfloat16 a, __nv_bfloat16 b) {
    return (uint32_t)__bfloat16_as_ushort(a) |
           ((uint32_t)__bfloat16_as_ushort(b) << 16);
}

// Split x = hi + lo (both bf16) ; returns packed pairs for 4 floats
__device__ __forceinline__ void split4(float4 v, uint32_t hi[2], uint32_t lo[2]) {
    __nv_bfloat16 hx = __float2bfloat16(v.x);
    __nv_bfloat16 hy = __float2bfloat16(v.y);
    __nv_bfloat16 hz = __float2bfloat16(v.z);
    __nv_bfloat16 hw = __float2bfloat16(v.w);
    __nv_bfloat16 lx = __float2bfloat16(v.x - __bfloat162float(hx));
    __nv_bfloat16 ly = __float2bfloat16(v.y - __bfloat162float(hy));
    __nv_bfloat16 lz = __float2bfloat16(v.z - __bfloat162float(hz));
    __nv_bfloat16 lw = __float2bfloat16(v.w - __bfloat162float(hw));
    hi[0] = pack_bf16x2(hx, hy); hi[1] = pack_bf16x2(hz, hw);
    lo[0] = pack_bf16x2(lx, ly); lo[1] = pack_bf16x2(lz, lw);
}

// ---------------------------------------------------------------------------
// bf16x3 split GEMM: C[M,N] = A[M,K] @ B[N,K]^T (row-major), fp32-class accuracy
// CTA tile 128x128, BK=32, 256 threads, warp tile 32x64 (4x2 warps)
// Smem: one stage; A/B each hi+lo, 128 rows x 32 cols bf16, row stride 40 elems
// ---------------------------------------------------------------------------
#define GS 40                    // smem row stride (elements)
#define TILE_HALF (128 * GS)     // one matrix-half (hi or lo) in bf16 elems

__global__ __launch_bounds__(256) void gemm_bf16x3(
    const float* __restrict__ A, const float* __restrict__ B,
    float* __restrict__ C, int M, int N, int K)
{
    __shared__ __align__(16) uint16_t sm[4 * TILE_HALF];  // Ah, Al, Bh, Bl

    const int tid = threadIdx.x;
    const int wid = tid >> 5;
    const int lid = tid & 31;
    const int wm  = wid & 3;        // 0..3 -> M offset wm*32
    const int wn  = wid >> 2;       // 0..1 -> N offset wn*64
    const int bm  = blockIdx.y * 128;
    const int bn  = blockIdx.x * 128;

    const uint32_t sAh = smem_u32(sm);
    const uint32_t sAl = sAh + TILE_HALF * 2;
    const uint32_t sBh = sAh + 2 * TILE_HALF * 2;
    const uint32_t sBl = sAh + 3 * TILE_HALF * 2;

    // ldmatrix per-lane geometry
    const int mm = lid >> 3, lr = lid & 7;
    const int a_row = ((mm & 1) << 3) + lr;   // row within m16 tile
    const int a_k   = (mm >> 1) << 3;         // 0 or 8
    const int b_row = ((mm >> 1) << 3) + lr;  // n within 2-tile group
    const int b_k   = (mm & 1) << 3;

    // Gmem load geometry: 4 float4 from each of A,B per chunk per thread
    const float* pA[4];
    const float* pB[4];
    uint32_t so[4];                 // smem element offset (row*GS + k)
    #pragma unroll
    for (int j = 0; j < 4; j++) {
        int f = tid + j * 256;      // 0..1023
        int r = f >> 3, c4 = f & 7;
        pA[j] = A + (size_t)(bm + r) * K + c4 * 4;
        pB[j] = B + (size_t)(bn + r) * K + c4 * 4;
        so[j] = r * GS + c4 * 4;
    }

    const int NCH = K / 32;
    float4 cA[4], cB[4];
    #pragma unroll
    for (int j = 0; j < 4; j++) { cA[j] = *(const float4*)pA[j]; cB[j] = *(const float4*)pB[j]; }

    float acc[2][8][4];
    #pragma unroll
    for (int i = 0; i < 2; i++)
        #pragma unroll
        for (int j = 0; j < 8; j++)
            #pragma unroll
            for (int t = 0; t < 4; t++) acc[i][j][t] = 0.f;

    for (int ch = 0; ch < NCH; ch++) {
        // Convert current chunk and store hi/lo to smem
        #pragma unroll
        for (int j = 0; j < 4; j++) {
            uint32_t h[2], l[2];
            split4(cA[j], h, l);
            *(uint2*)((uint16_t*)sm + so[j])               = make_uint2(h[0], h[1]);
            *(uint2*)((uint16_t*)sm + TILE_HALF + so[j])   = make_uint2(l[0], l[1]);
            split4(cB[j], h, l);
            *(uint2*)((uint16_t*)sm + 2*TILE_HALF + so[j]) = make_uint2(h[0], h[1]);
            *(uint2*)((uint16_t*)sm + 3*TILE_HALF + so[j]) = make_uint2(l[0], l[1]);
        }
        __syncthreads();

        // Prefetch next chunk (overlaps with HMMA below)
        if (ch + 1 < NCH) {
            #pragma unroll
            for (int j = 0; j < 4; j++) {
                cA[j] = *(const float4*)(pA[j] + (ch + 1) * 32);
                cB[j] = *(const float4*)(pB[j] + (ch + 1) * 32);
            }
        }

        // Compute: 2 x k16 steps, 3 split passes each
        #pragma unroll
        for (int kk = 0; kk < 32; kk += 16) {
            uint32_t ah[2][4], al[2][4], bb[4][4];
            uint32_t boff[4];
            #pragma unroll
            for (int i = 0; i < 2; i++) {
                uint32_t off = ((wm*32 + i*16 + a_row) * GS + kk + a_k) * 2;
                LDM4(ah[i], sAh + off);
                LDM4(al[i], sAl + off);
            }
            #pragma unroll
            for (int j = 0; j < 4; j++) {
                boff[j] = ((wn*64 + j*16 + b_row) * GS + kk + b_k) * 2;
                LDM4(bb[j], sBh + boff[j]);
            }
            // pass 1: Ahi * Bhi
            #pragma unroll
            for (int i = 0; i < 2; i++)
                #pragma unroll
                for (int j = 0; j < 8; j++)
                    mma_bf16(acc[i][j], ah[i], &bb[j>>1][(j&1)*2]);
            // pass 2: Alo * Bhi (Bhi still resident)
            #pragma unroll
            for (int i = 0; i < 2; i++)
                #pragma unroll
                for (int j = 0; j < 8; j++)
                    mma_bf16(acc[i][j], al[i], &bb[j>>1][(j&1)*2]);
            // pass 3: Ahi * Blo
            #pragma unroll
            for (int j = 0; j < 4; j++) LDM4(bb[j], sBl + boff[j]);
            #pragma unroll
            for (int i = 0; i < 2; i++)
                #pragma unroll
                for (int j = 0; j < 8; j++)
                    mma_bf16(acc[i][j], ah[i], &bb[j>>1][(j&1)*2]);
        }
        __syncthreads();
    }

    // Epilogue
    const int r0 = bm + wm*32 + (lid >> 2);
    const int c0 = bn + wn*64 + (lid & 3) * 2;
    #pragma unroll
    for (int i = 0; i < 2; i++)
        #pragma unroll
        for (int j = 0; j < 8; j++) {
            int r = r0 + i*16, c = c0 + j*8;
            *(float2*)&C[(size_t)r * N + c]       = make_float2(acc[i][j][0], acc[i][j][1]);
            *(float2*)&C[(size_t)(r+8) * N + c]   = make_float2(acc[i][j][2], acc[i][j][3]);
        }
}

// ---------------------------------------------------------------------------
// RoPE (in-place), optional scale folded in (1/sqrt(D) for Q)
// ---------------------------------------------------------------------------
__global__ void rope_kernel(float* __restrict__ X,
                            const float* __restrict__ cosb,
                            const float* __restrict__ sinb,
                            int nheads, float scale)
{
    int idx = blockIdx.x * blockDim.x + threadIdx.x;
    int total = SEQ * nheads * 64;
    if (idx >= total) return;
    int d = idx & 63;
    int h = (idx >> 6) % nheads;
    int s = idx / (nheads * 64);
    float c  = cosb[s * 128 + d];
    float sn = sinb[s * 128 + d];
    float* p = X + (size_t)s * nheads * DH + h * DH;
    float x0 = p[d], x1 = p[d + 64];
    p[d]      = (x0 * c - x1 * sn) * scale;
    p[d + 64] = (x1 * c + x0 * sn) * scale;
}

// ---------------------------------------------------------------------------
// Flash attention, fp32, causal, GQA (kv head = qhead >> 2). (R1 kernel)
// ---------------------------------------------------------------------------
#define FBR 64
#define FBC 64
#define SS_STRIDE 65
#define FLASH_SMEM ((128*64*2 + 64*128 + 64*SS_STRIDE + 3*64) * 4)

__global__ __launch_bounds__(256) void flash_attn(
    const float* __restrict__ Q, const float* __restrict__ K,
    const float* __restrict__ V, float* __restrict__ O)
{
    extern __shared__ float sm[];
    float* QsT = sm;
    float* KsT = QsT + 128*64;
    float* Vs  = KsT + 128*64;
    float* Ss  = Vs  + 64*128;
    float* ms  = Ss  + 64*SS_STRIDE;
    float* ls  = ms + 64;
    float* cr  = ls + 64;

    const int tid = threadIdx.x;
    const int qt  = blockIdx.x;
    const int h   = blockIdx.y;
    const int kvh = h >> 2;
    const int q0  = qt * FBR;
    const int tx  = tid & 15;
    const int ty  = tid >> 4;
    const int orow = tid & 63;
    const int och  = tid >> 6;

    for (int idx = tid; idx < 64 * 32; idx += 256) {
        int r = idx & 63, d4 = idx >> 6;
        float4 v = *(const float4*)(Q + (size_t)(q0 + r) * QDIM + h * DH + d4 * 4);
        QsT[(d4*4+0)*64 + r] = v.x;
        QsT[(d4*4+1)*64 + r] = v.y;
        QsT[(d4*4+2)*64 + r] = v.z;
        QsT[(d4*4+3)*64 + r] = v.w;
    }
    if (tid < 64) { ms[tid] = -1e30f; ls[tid] = 0.f; }

    float acc[32];
    #pragma unroll
    for (int i = 0; i < 32; i++) acc[i] = 0.f;

    for (int kt = 0; kt <= qt; kt++) {
        const int k0 = kt * FBC;

        for (int idx = tid; idx < 64 * 32; idx += 256) {
            int c = idx & 63, d4 = idx >> 6;
            float4 v = *(const float4*)(K + (size_t)(k0 + c) * KVDIM + kvh * DH + d4 * 4);
            KsT[(d4*4+0)*64 + c] = v.x;
            KsT[(d4*4+1)*64 + c] = v.y;
            KsT[(d4*4+2)*64 + c] = v.z;
            KsT[(d4*4+3)*64 + c] = v.w;
        }
        __syncthreads();

        float s4[4][4];
        #pragma unroll
        for (int i = 0; i < 4; i++)
            #pragma unroll
            for (int j = 0; j < 4; j++) s4[i][j] = 0.f;

        #pragma unroll 8
        for (int kk = 0; kk < DH; kk++) {
            float4 qv = *(const float4*)&QsT[kk*64 + ty*4];
            float4 kv = *(const float4*)&KsT[kk*64 + tx*4];
            float qa[4] = {qv.x, qv.y, qv.z, qv.w};
            float ka[4] = {kv.x, kv.y, kv.z, kv.w};
            #pragma unroll
            for (int i = 0; i < 4; i++)
                #pragma unroll
                for (int j = 0; j < 4; j++)
                    s4[i][j] = fmaf(qa[i], ka[j], s4[i][j]);
        }
        #pragma unroll
        for (int i = 0; i < 4; i++)
            #pragma unroll
            for (int j = 0; j < 4; j++)
                Ss[(ty*4+i)*SS_STRIDE + tx*4 + j] = s4[i][j];
        __syncthreads();

        for (int idx = tid; idx < 64 * 32; idx += 256) {
            int c = idx >> 5, d4 = idx & 31;
            *(float4*)&Vs[c*128 + d4*4] =
                *(const float4*)(V + (size_t)(k0 + c) * KVDIM + kvh * DH + d4 * 4);
        }
        if (tid < 64) {
            int r = tid;
            int lim = (kt == qt) ? (r + 1) : FBC;
            float mold = ms[r];
            float m = mold;
            for (int c = 0; c < lim; c++) m = fmaxf(m, Ss[r*SS_STRIDE + c]);
            float corr = __expf(mold - m);
            float l = ls[r] * corr;
            for (int c = 0; c < FBC; c++) {
                float p = (c < lim) ? __expf(Ss[r*SS_STRIDE + c] - m) : 0.f;
                Ss[r*SS_STRIDE + c] = p;
                l += p;
            }
            ms[r] = m; ls[r] = l; cr[r] = corr;
        }
        __syncthreads();

        float corr = cr[orow];
        #pragma unroll
        for (int i = 0; i < 32; i++) acc[i] *= corr;

        for (int c = 0; c < FBC; c++) {
            float p = Ss[orow*SS_STRIDE + c];
            const float* vrow = &Vs[c*128 + och*32];
            #pragma unroll
            for (int d4 = 0; d4 < 8; d4++) {
                float4 v = *(const float4*)(vrow + d4*4);
                acc[d4*4+0] = fmaf(p, v.x, acc[d4*4+0]);
                acc[d4*4+1] = fmaf(p, v.y, acc[d4*4+1]);
                acc[d4*4+2] = fmaf(p, v.z, acc[d4*4+2]);
                acc[d4*4+3] = fmaf(p, v.w, acc[d4*4+3]);
            }
        }
        __syncthreads();
    }

    float inv = 1.0f / ls[orow];
    float* Op = O + (size_t)(q0 + orow) * QDIM + h * DH + och * 32;
    #pragma unroll
    for (int d4 = 0; d4 < 8; d4++) {
        float4 v = make_float4(acc[d4*4+0]*inv, acc[d4*4+1]*inv,
                               acc[d4*4+2]*inv, acc[d4*4+3]*inv);
        *(float4*)(Op + d4*4) = v;
    }
}

// ---------------------------------------------------------------------------
// Launch
// ---------------------------------------------------------------------------
extern "C" void kernel_launch(void* const* d_in, const int* in_sizes, int n_in,
                              void* d_out, int out_size)
{
    const float* hidden = (const float*)d_in[0];
    const float* cosb   = (const float*)d_in[1];
    const float* sinb   = (const float*)d_in[2];
    // d_in[3] = attention_mask (pure causal; applied analytically)
    const float* Wq     = (const float*)d_in[4];
    const float* Wk     = (const float*)d_in[5];
    const float* Wv     = (const float*)d_in[6];
    const float* Wo     = (const float*)d_in[7];
    float* out = (float*)d_out;

    float *qp, *kp, *vp, *aop;
    cudaGetSymbolAddress((void**)&qp,  g_q);
    cudaGetSymbolAddress((void**)&kp,  g_k);
    cudaGetSymbolAddress((void**)&vp,  g_v);
    cudaGetSymbolAddress((void**)&aop, g_ao);

    cudaFuncSetAttribute(flash_attn, cudaFuncAttributeMaxDynamicSharedMemorySize,
                         FLASH_SMEM);

    // Projections (tensor cores via mma.sync, bf16 split x3)
    gemm_bf16x3<<<dim3(QDIM/128,  SEQ/128), 256>>>(hidden, Wq, qp, SEQ, QDIM,  HID);
    gemm_bf16x3<<<dim3(KVDIM/128, SEQ/128), 256>>>(hidden, Wk, kp, SEQ, KVDIM, HID);
    gemm_bf16x3<<<dim3(KVDIM/128, SEQ/128), 256>>>(hidden, Wv, vp, SEQ, KVDIM, HID);

    // RoPE (Q also gets 1/sqrt(D) folded in)
    const float scale = 0.08838834764831845f;   // 128^-0.5
    rope_kernel<<<(SEQ*NH*64 + 255)/256, 256>>>(qp, cosb, sinb, NH,  scale);
    rope_kernel<<<(SEQ*NKV*64 + 255)/256, 256>>>(kp, cosb, sinb, NKV, 1.0f);

    // Flash attention (SIMT fp32; mma.sync port is the next step)
    flash_attn<<<dim3(SEQ/FBR, NH), 256, FLASH_SMEM>>>(qp, kp, vp, aop);

    // Output projection
    gemm_bf16x3<<<dim3(QDIM/128, SEQ/128), 256>>>(aop, Wo, out, SEQ, QDIM, HID);
}

// round 5
// speedup vs baseline: 2.4840x; 1.3436x over previous
#include <cuda_runtime.h>
#include <cuda_bf16.h>
#include <cstdint>
#include <math.h>

// Problem constants
#define SEQ   2048
#define HID   4096
#define NH    32
#define NKV   8
#define DH    128
#define QDIM  (NH * DH)    // 4096
#define KVDIM (NKV * DH)   // 1024

// Scratch (device globals; allocation is forbidden)
__device__ float g_q [SEQ * QDIM];
__device__ float g_k [SEQ * KVDIM];
__device__ float g_v [SEQ * KVDIM];
__device__ float g_ao[SEQ * QDIM];
__device__ __nv_bfloat16 g_qh[SEQ * QDIM];
__device__ __nv_bfloat16 g_ql[SEQ * QDIM];
__device__ __nv_bfloat16 g_kh[SEQ * KVDIM];
__device__ __nv_bfloat16 g_kl[SEQ * KVDIM];
__device__ __nv_bfloat16 g_vh[SEQ * KVDIM];
__device__ __nv_bfloat16 g_vl[SEQ * KVDIM];

// ---------------------------------------------------------------------------
// Helpers: mma.sync bf16 (legacy HMMA path — compiles for plain sm_100)
// ---------------------------------------------------------------------------
__device__ __forceinline__ uint32_t smem_u32(const void* p) {
    uint32_t a;
    asm("{ .reg .u64 t; cvta.to.shared.u64 t, %1; cvt.u32.u64 %0, t; }"
        : "=r"(a) : "l"(p));
    return a;
}

#define LDM4(r, addr)                                                         \
    asm volatile("ldmatrix.sync.aligned.m8n8.x4.shared.b16 {%0,%1,%2,%3}, [%4];" \
                 : "=r"((r)[0]), "=r"((r)[1]), "=r"((r)[2]), "=r"((r)[3])     \
                 : "r"(addr))
#define LDM4T(r, addr)                                                        \
    asm volatile("ldmatrix.sync.aligned.m8n8.x4.trans.shared.b16 {%0,%1,%2,%3}, [%4];" \
                 : "=r"((r)[0]), "=r"((r)[1]), "=r"((r)[2]), "=r"((r)[3])     \
                 : "r"(addr))

__device__ __forceinline__ void mma_bf16(float* c, const uint32_t* a,
                                         const uint32_t* b) {
    asm volatile(
        "mma.sync.aligned.m16n8k16.row.col.f32.bf16.bf16.f32 "
        "{%0,%1,%2,%3}, {%4,%5,%6,%7}, {%8,%9}, {%0,%1,%2,%3};"
        : "+f"(c[0]), "+f"(c[1]), "+f"(c[2]), "+f"(c[3])
        : "r"(a[0]), "r"(a[1]), "r"(a[2]), "r"(a[3]), "r"(b[0]), "r"(b[1]));
}

__device__ __forceinline__ uint32_t pack_bf16x2(__nv_bfloat16 a, __nv_bfloat16 b) {
    return (uint32_t)__bfloat16_as_ushort(a) |
           ((uint32_t)__bfloat16_as_ushort(b) << 16);
}

__device__ __forceinline__ void split4(float4 v, uint32_t hi[2], uint32_t lo[2]) {
    __nv_bfloat16 hx = __float2bfloat16(v.x);
    __nv_bfloat16 hy = __float2bfloat16(v.y);
    __nv_bfloat16 hz = __float2bfloat16(v.z);
    __nv_bfloat16 hw = __float2bfloat16(v.w);
    __nv_bfloat16 lx = __float2bfloat16(v.x - __bfloat162float(hx));
    __nv_bfloat16 ly = __float2bfloat16(v.y - __bfloat162float(hy));
    __nv_bfloat16 lz = __float2bfloat16(v.z - __bfloat162float(hz));
    __nv_bfloat16 lw = __float2bfloat16(v.w - __bfloat162float(hw));
    hi[0] = pack_bf16x2(hx, hy); hi[1] = pack_bf16x2(hz, hw);
    lo[0] = pack_bf16x2(lx, ly); lo[1] = pack_bf16x2(lz, lw);
}

// ---------------------------------------------------------------------------
// bf16x3 split GEMM (unchanged from R4 — verified)
// ---------------------------------------------------------------------------
#define GS 40
#define TILE_HALF (128 * GS)

__global__ __launch_bounds__(256) void gemm_bf16x3(
    const float* __restrict__ A, const float* __restrict__ B,
    float* __restrict__ C, int M, int N, int K)
{
    __shared__ __align__(16) uint16_t sm[4 * TILE_HALF];

    const int tid = threadIdx.x;
    const int wid = tid >> 5;
    const int lid = tid & 31;
    const int wm  = wid & 3;
    const int wn  = wid >> 2;
    const int bm  = blockIdx.y * 128;
    const int bn  = blockIdx.x * 128;

    const uint32_t sAh = smem_u32(sm);
    const uint32_t sAl = sAh + TILE_HALF * 2;
    const uint32_t sBh = sAh + 2 * TILE_HALF * 2;
    const uint32_t sBl = sAh + 3 * TILE_HALF * 2;

    const int mm = lid >> 3, lr = lid & 7;
    const int a_row = ((mm & 1) << 3) + lr;
    const int a_k   = (mm >> 1) << 3;
    const int b_row = ((mm >> 1) << 3) + lr;
    const int b_k   = (mm & 1) << 3;

    const float* pA[4];
    const float* pB[4];
    uint32_t so[4];
    #pragma unroll
    for (int j = 0; j < 4; j++) {
        int f = tid + j * 256;
        int r = f >> 3, c4 = f & 7;
        pA[j] = A + (size_t)(bm + r) * K + c4 * 4;
        pB[j] = B + (size_t)(bn + r) * K + c4 * 4;
        so[j] = r * GS + c4 * 4;
    }

    const int NCH = K / 32;
    float4 cA[4], cB[4];
    #pragma unroll
    for (int j = 0; j < 4; j++) { cA[j] = *(const float4*)pA[j]; cB[j] = *(const float4*)pB[j]; }

    float acc[2][8][4];
    #pragma unroll
    for (int i = 0; i < 2; i++)
        #pragma unroll
        for (int j = 0; j < 8; j++)
            #pragma unroll
            for (int t = 0; t < 4; t++) acc[i][j][t] = 0.f;

    for (int ch = 0; ch < NCH; ch++) {
        #pragma unroll
        for (int j = 0; j < 4; j++) {
            uint32_t h[2], l[2];
            split4(cA[j], h, l);
            *(uint2*)((uint16_t*)sm + so[j])               = make_uint2(h[0], h[1]);
            *(uint2*)((uint16_t*)sm + TILE_HALF + so[j])   = make_uint2(l[0], l[1]);
            split4(cB[j], h, l);
            *(uint2*)((uint16_t*)sm + 2*TILE_HALF + so[j]) = make_uint2(h[0], h[1]);
            *(uint2*)((uint16_t*)sm + 3*TILE_HALF + so[j]) = make_uint2(l[0], l[1]);
        }
        __syncthreads();

        if (ch + 1 < NCH) {
            #pragma unroll
            for (int j = 0; j < 4; j++) {
                cA[j] = *(const float4*)(pA[j] + (ch + 1) * 32);
                cB[j] = *(const float4*)(pB[j] + (ch + 1) * 32);
            }
        }

        #pragma unroll
        for (int kk = 0; kk < 32; kk += 16) {
            uint32_t ah[2][4], al[2][4], bb[4][4];
            uint32_t boff[4];
            #pragma unroll
            for (int i = 0; i < 2; i++) {
                uint32_t off = ((wm*32 + i*16 + a_row) * GS + kk + a_k) * 2;
                LDM4(ah[i], sAh + off);
                LDM4(al[i], sAl + off);
            }
            #pragma unroll
            for (int j = 0; j < 4; j++) {
                boff[j] = ((wn*64 + j*16 + b_row) * GS + kk + b_k) * 2;
                LDM4(bb[j], sBh + boff[j]);
            }
            #pragma unroll
            for (int i = 0; i < 2; i++)
                #pragma unroll
                for (int j = 0; j < 8; j++)
                    mma_bf16(acc[i][j], ah[i], &bb[j>>1][(j&1)*2]);
            #pragma unroll
            for (int i = 0; i < 2; i++)
                #pragma unroll
                for (int j = 0; j < 8; j++)
                    mma_bf16(acc[i][j], al[i], &bb[j>>1][(j&1)*2]);
            #pragma unroll
            for (int j = 0; j < 4; j++) LDM4(bb[j], sBl + boff[j]);
            #pragma unroll
            for (int i = 0; i < 2; i++)
                #pragma unroll
                for (int j = 0; j < 8; j++)
                    mma_bf16(acc[i][j], ah[i], &bb[j>>1][(j&1)*2]);
        }
        __syncthreads();
    }

    const int r0 = bm + wm*32 + (lid >> 2);
    const int c0 = bn + wn*64 + (lid & 3) * 2;
    #pragma unroll
    for (int i = 0; i < 2; i++)
        #pragma unroll
        for (int j = 0; j < 8; j++) {
            int r = r0 + i*16, c = c0 + j*8;
            *(float2*)&C[(size_t)r * N + c]       = make_float2(acc[i][j][0], acc[i][j][1]);
            *(float2*)&C[(size_t)(r+8) * N + c]   = make_float2(acc[i][j][2], acc[i][j][3]);
        }
}

// ---------------------------------------------------------------------------
// RoPE + bf16 hi/lo split (scale folded in for Q)
// ---------------------------------------------------------------------------
__global__ void rope_split(const float* __restrict__ X,
                           __nv_bfloat16* __restrict__ Xh,
                           __nv_bfloat16* __restrict__ Xl,
                           const float* __restrict__ cosb,
                           const float* __restrict__ sinb,
                           int nheads, float scale)
{
    int idx = blockIdx.x * blockDim.x + threadIdx.x;
    int total = SEQ * nheads * 64;
    if (idx >= total) return;
    int d = idx & 63;
    int h = (idx >> 6) % nheads;
    int s = idx / (nheads * 64);
    float c  = cosb[s * 128 + d];
    float sn = sinb[s * 128 + d];
    size_t base = ((size_t)s * nheads + h) * DH;
    float x0 = X[base + d], x1 = X[base + d + 64];
    float y0 = (x0 * c - x1 * sn) * scale;
    float y1 = (x1 * c + x0 * sn) * scale;
    __nv_bfloat16 h0 = __float2bfloat16(y0);
    __nv_bfloat16 h1 = __float2bfloat16(y1);
    Xh[base + d]      = h0;
    Xh[base + d + 64] = h1;
    Xl[base + d]      = __float2bfloat16(y0 - __bfloat162float(h0));
    Xl[base + d + 64] = __float2bfloat16(y1 - __bfloat162float(h1));
}

__global__ void v_split(const float* __restrict__ X,
                        __nv_bfloat16* __restrict__ Xh,
                        __nv_bfloat16* __restrict__ Xl, int n)
{
    int idx = blockIdx.x * blockDim.x + threadIdx.x;
    if (idx >= n) return;
    float x = X[idx];
    __nv_bfloat16 h = __float2bfloat16(x);
    Xh[idx] = h;
    Xl[idx] = __float2bfloat16(x - __bfloat162float(h));
}

// ---------------------------------------------------------------------------
// Flash attention via mma.sync bf16-split. Causal, GQA (kv head = qhead>>2).
// CTA: 64 q-rows x one head, 256 threads (8 warps, 4x2).
// Q pre-scaled by 1/sqrt(D) in rope_split.
// ---------------------------------------------------------------------------
#define FS2 136                 // Q/K/V smem row stride (elems)
#define FPS 72                  // P smem row stride (elems)
#define FTB (64 * FS2)          // tile elems (bf16)
// byte offsets within dynamic smem
#define OFF_QH 0
#define OFF_QL (OFF_QH + FTB*2)
#define OFF_KH (OFF_QL + FTB*2)
#define OFF_KL (OFF_KH + FTB*2)
#define OFF_VH (OFF_KL + FTB*2)
#define OFF_VL (OFF_VH + FTB*2)
#define OFF_SS (OFF_VL + FTB*2)              // fp32 [64][66]
#define OFF_PH (OFF_SS + 64*66*4)
#define OFF_PL (OFF_PH + 64*FPS*2)
#define OFF_PM (OFF_PL + 64*FPS*2)           // fp32 [4][64]
#define OFF_PS (OFF_PM + 4*64*4)             // fp32 [4][64]
#define OFF_MS (OFF_PS + 4*64*4)             // fp32 [64]
#define OFF_LS (OFF_MS + 64*4)
#define OFF_CR (OFF_LS + 64*4)
#define OFF_MN (OFF_CR + 64*4)
#define FLASH2_SMEM (OFF_MN + 64*4)

__global__ __launch_bounds__(256) void flash_mma(
    const __nv_bfloat16* __restrict__ Qh, const __nv_bfloat16* __restrict__ Ql,
    const __nv_bfloat16* __restrict__ Kh, const __nv_bfloat16* __restrict__ Kl,
    const __nv_bfloat16* __restrict__ Vh, const __nv_bfloat16* __restrict__ Vl,
    float* __restrict__ O)
{
    extern __shared__ char fsm[];
    const uint32_t sb = smem_u32(fsm);
    __nv_bfloat16* sQh = (__nv_bfloat16*)(fsm + OFF_QH);
    __nv_bfloat16* sQl = (__nv_bfloat16*)(fsm + OFF_QL);
    __nv_bfloat16* sKh = (__nv_bfloat16*)(fsm + OFF_KH);
    __nv_bfloat16* sKl = (__nv_bfloat16*)(fsm + OFF_KL);
    __nv_bfloat16* sVh = (__nv_bfloat16*)(fsm + OFF_VH);
    __nv_bfloat16* sVl = (__nv_bfloat16*)(fsm + OFF_VL);
    float* Ss = (float*)(fsm + OFF_SS);
    __nv_bfloat16* Ph = (__nv_bfloat16*)(fsm + OFF_PH);
    __nv_bfloat16* Pl = (__nv_bfloat16*)(fsm + OFF_PL);
    float* pm = (float*)(fsm + OFF_PM);
    float* ps = (float*)(fsm + OFF_PS);
    float* ms = (float*)(fsm + OFF_MS);
    float* ls = (float*)(fsm + OFF_LS);
    float* cr = (float*)(fsm + OFF_CR);
    float* mn = (float*)(fsm + OFF_MN);

    const int tid = threadIdx.x;
    const int wid = tid >> 5;
    const int lid = tid & 31;
    const int wm  = wid & 3;         // score rows wm*16; PV rows wm*16
    const int wn  = wid >> 2;        // score cols wn*32; PV cols wn*64
    const int qt  = gridDim.x - 1 - blockIdx.x;   // heavy tiles first
    const int h   = blockIdx.y;
    const int kvh = h >> 2;
    const int q0  = qt * 64;

    const int mm = lid >> 3, lr = lid & 7;
    const int a_row = ((mm & 1) << 3) + lr;
    const int a_k   = (mm >> 1) << 3;
    const int b_row = ((mm >> 1) << 3) + lr;
    const int b_k   = (mm & 1) << 3;
    // V trans-load geometry
    const int v_k = ((mm & 1) << 3) + lr;
    const int v_n = (mm >> 1) << 3;

    // Load Q tile (hi+lo): 64 rows x 128 cols bf16 -> 16 uint4 rows chunks
    for (int i = tid; i < 64 * 16; i += 256) {
        int r = i >> 4, c8 = i & 15;
        size_t gb = (((size_t)(q0 + r) * NH + h) * DH + c8 * 8);
        *(uint4*)(sQh + r * FS2 + c8 * 8) = *(const uint4*)(Qh + gb);
        *(uint4*)(sQl + r * FS2 + c8 * 8) = *(const uint4*)(Ql + gb);
    }
    if (tid < 64) { ms[tid] = -1e30f; ls[tid] = 0.f; }

    float oacc[8][4];
    #pragma unroll
    for (int j = 0; j < 8; j++)
        #pragma unroll
        for (int t = 0; t < 4; t++) oacc[j][t] = 0.f;

    for (int kt = 0; kt <= qt; kt++) {
        const int k0 = kt * 64;
        // Load K,V tiles (hi+lo)
        for (int i = tid; i < 64 * 16; i += 256) {
            int r = i >> 4, c8 = i & 15;
            size_t gb = (((size_t)(k0 + r) * NKV + kvh) * DH + c8 * 8);
            *(uint4*)(sKh + r * FS2 + c8 * 8) = *(const uint4*)(Kh + gb);
            *(uint4*)(sKl + r * FS2 + c8 * 8) = *(const uint4*)(Kl + gb);
            *(uint4*)(sVh + r * FS2 + c8 * 8) = *(const uint4*)(Vh + gb);
            *(uint4*)(sVl + r * FS2 + c8 * 8) = *(const uint4*)(Vl + gb);
        }
        __syncthreads();

        // ---- S = Q @ K^T (3-pass split), warp tile 16x32 ----
        float sacc[4][4];
        #pragma unroll
        for (int j = 0; j < 4; j++)
            #pragma unroll
            for (int t = 0; t < 4; t++) sacc[j][t] = 0.f;

        #pragma unroll
        for (int kk = 0; kk < 8; kk++) {
            uint32_t ah[4], al[4], bh[2][4], bl[2][4];
            uint32_t aoff = (uint32_t)((wm*16 + a_row) * FS2 + kk*16 + a_k) * 2;
            LDM4(ah, sb + OFF_QH + aoff);
            LDM4(al, sb + OFF_QL + aoff);
            uint32_t boff0 = (uint32_t)((wn*32 + b_row) * FS2 + kk*16 + b_k) * 2;
            uint32_t boff1 = (uint32_t)((wn*32 + 16 + b_row) * FS2 + kk*16 + b_k) * 2;
            LDM4(bh[0], sb + OFF_KH + boff0);
            LDM4(bh[1], sb + OFF_KH + boff1);
            LDM4(bl[0], sb + OFF_KL + boff0);
            LDM4(bl[1], sb + OFF_KL + boff1);
            #pragma unroll
            for (int j = 0; j < 4; j++) mma_bf16(sacc[j], ah, &bh[j>>1][(j&1)*2]);
            #pragma unroll
            for (int j = 0; j < 4; j++) mma_bf16(sacc[j], al, &bh[j>>1][(j&1)*2]);
            #pragma unroll
            for (int j = 0; j < 4; j++) mma_bf16(sacc[j], ah, &bl[j>>1][(j&1)*2]);
        }
        {
            int sr = wm*16 + (lid >> 2);
            int sc = wn*32 + (lid & 3) * 2;
            #pragma unroll
            for (int j = 0; j < 4; j++) {
                *(float2*)&Ss[sr*66 + sc + j*8]     = make_float2(sacc[j][0], sacc[j][1]);
                *(float2*)&Ss[(sr+8)*66 + sc + j*8] = make_float2(sacc[j][2], sacc[j][3]);
            }
        }
        __syncthreads();

        // ---- softmax: 4 threads per row ----
        {
            int r = tid & 63, qtr = tid >> 6;
            int lim = (kt == qt) ? (r + 1) : 64;
            int c0 = qtr * 16;
            float lmax = -1e30f;
            #pragma unroll
            for (int c = 0; c < 16; c++) {
                int cc = c0 + c;
                if (cc < lim) lmax = fmaxf(lmax, Ss[r*66 + cc]);
            }
            pm[qtr*64 + r] = lmax;
        }
        __syncthreads();
        if (tid < 64) {
            float mold = ms[tid];
            float m = mold;
            #pragma unroll
            for (int q = 0; q < 4; q++) m = fmaxf(m, pm[q*64 + tid]);
            mn[tid] = m;
            cr[tid] = __expf(mold - m);
        }
        __syncthreads();
        {
            int r = tid & 63, qtr = tid >> 6;
            int lim = (kt == qt) ? (r + 1) : 64;
            int c0 = qtr * 16;
            float m = mn[r];
            float lsum = 0.f;
            #pragma unroll
            for (int c = 0; c < 16; c++) {
                int cc = c0 + c;
                float p = (cc < lim) ? __expf(Ss[r*66 + cc] - m) : 0.f;
                __nv_bfloat16 ph = __float2bfloat16(p);
                Ph[r*FPS + cc] = ph;
                Pl[r*FPS + cc] = __float2bfloat16(p - __bfloat162float(ph));
                lsum += p;
            }
            ps[qtr*64 + r] = lsum;
        }
        __syncthreads();
        if (tid < 64) {
            float l = ls[tid] * cr[tid];
            #pragma unroll
            for (int q = 0; q < 4; q++) l += ps[q*64 + tid];
            ls[tid] = l;
            ms[tid] = mn[tid];
        }
        __syncthreads();

        // ---- O += P @ V (3-pass split), warp tile 16x64 ----
        {
            float c0f = cr[wm*16 + (lid >> 2)];
            float c1f = cr[wm*16 + (lid >> 2) + 8];
            #pragma unroll
            for (int j = 0; j < 8; j++) {
                oacc[j][0] *= c0f; oacc[j][1] *= c0f;
                oacc[j][2] *= c1f; oacc[j][3] *= c1f;
            }
        }
        #pragma unroll
        for (int kk = 0; kk < 4; kk++) {
            uint32_t aph[4], apl[4], vv[4][4];
            uint32_t aoff = (uint32_t)((wm*16 + a_row) * FPS + kk*16 + a_k) * 2;
            LDM4(aph, sb + OFF_PH + aoff);
            LDM4(apl, sb + OFF_PL + aoff);
            uint32_t voff[4];
            #pragma unroll
            for (int t = 0; t < 4; t++) {
                voff[t] = (uint32_t)((kk*16 + v_k) * FS2 + wn*64 + t*16 + v_n) * 2;
                LDM4T(vv[t], sb + OFF_VH + voff[t]);
            }
            #pragma unroll
            for (int j = 0; j < 8; j++) mma_bf16(oacc[j], aph, &vv[j>>1][(j&1)*2]);
            #pragma unroll
            for (int j = 0; j < 8; j++) mma_bf16(oacc[j], apl, &vv[j>>1][(j&1)*2]);
            #pragma unroll
            for (int t = 0; t < 4; t++) LDM4T(vv[t], sb + OFF_VL + voff[t]);
            #pragma unroll
            for (int j = 0; j < 8; j++) mma_bf16(oacc[j], aph, &vv[j>>1][(j&1)*2]);
        }
        __syncthreads();   // before next tile overwrites K/V/P smem
    }

    // Epilogue
    {
        float inv0 = 1.0f / ls[wm*16 + (lid >> 2)];
        float inv1 = 1.0f / ls[wm*16 + (lid >> 2) + 8];
        int gr = q0 + wm*16 + (lid >> 2);
        int gc = wn*64 + (lid & 3) * 2;
        #pragma unroll
        for (int j = 0; j < 8; j++) {
            *(float2*)&O[((size_t)gr * NH + h) * DH + gc + j*8] =
                make_float2(oacc[j][0]*inv0, oacc[j][1]*inv0);
            *(float2*)&O[((size_t)(gr+8) * NH + h) * DH + gc + j*8] =
                make_float2(oacc[j][2]*inv1, oacc[j][3]*inv1);
        }
    }
}

// ---------------------------------------------------------------------------
// Launch
// ---------------------------------------------------------------------------
extern "C" void kernel_launch(void* const* d_in, const int* in_sizes, int n_in,
                              void* d_out, int out_size)
{
    const float* hidden = (const float*)d_in[0];
    const float* cosb   = (const float*)d_in[1];
    const float* sinb   = (const float*)d_in[2];
    // d_in[3] = attention_mask (pure causal; applied analytically)
    const float* Wq     = (const float*)d_in[4];
    const float* Wk     = (const float*)d_in[5];
    const float* Wv     = (const float*)d_in[6];
    const float* Wo     = (const float*)d_in[7];
    float* out = (float*)d_out;

    float *qp, *kp, *vp, *aop;
    cudaGetSymbolAddress((void**)&qp,  g_q);
    cudaGetSymbolAddress((void**)&kp,  g_k);
    cudaGetSymbolAddress((void**)&vp,  g_v);
    cudaGetSymbolAddress((void**)&aop, g_ao);
    __nv_bfloat16 *qh, *ql, *kh, *kl, *vh, *vl;
    cudaGetSymbolAddress((void**)&qh, g_qh);
    cudaGetSymbolAddress((void**)&ql, g_ql);
    cudaGetSymbolAddress((void**)&kh, g_kh);
    cudaGetSymbolAddress((void**)&kl, g_kl);
    cudaGetSymbolAddress((void**)&vh, g_vh);
    cudaGetSymbolAddress((void**)&vl, g_vl);

    static bool attr_done = false;
    if (!attr_done) {
        cudaFuncSetAttribute(flash_mma, cudaFuncAttributeMaxDynamicSharedMemorySize,
                             FLASH2_SMEM);
        attr_done = true;
    }

    // Projections (tensor cores via mma.sync, bf16 split x3)
    gemm_bf16x3<<<dim3(QDIM/128,  SEQ/128), 256>>>(hidden, Wq, qp, SEQ, QDIM,  HID);
    gemm_bf16x3<<<dim3(KVDIM/128, SEQ/128), 256>>>(hidden, Wk, kp, SEQ, KVDIM, HID);
    gemm_bf16x3<<<dim3(KVDIM/128, SEQ/128), 256>>>(hidden, Wv, vp, SEQ, KVDIM, HID);

    // RoPE + bf16 split (Q also gets 1/sqrt(D) folded in)
    const float scale = 0.08838834764831845f;   // 128^-0.5
    rope_split<<<(SEQ*NH*64 + 255)/256, 256>>>(qp, qh, ql, cosb, sinb, NH,  scale);
    rope_split<<<(SEQ*NKV*64 + 255)/256, 256>>>(kp, kh, kl, cosb, sinb, NKV, 1.0f);
    v_split<<<(SEQ*KVDIM + 255)/256, 256>>>(vp, vh, vl, SEQ*KVDIM);

    // Flash attention (tensor cores)
    flash_mma<<<dim3(SEQ/64, NH), 256, FLASH2_SMEM>>>(qh, ql, kh, kl, vh, vl, aop);

    // Output projection
    gemm_bf16x3<<<dim3(QDIM/128, SEQ/128), 256>>>(aop, Wo, out, SEQ, QDIM, HID);
}

// round 6
// speedup vs baseline: 3.0239x; 1.2174x over previous
#include <cuda_runtime.h>
#include <cuda_bf16.h>
#include <cstdint>
#include <math.h>

// Problem constants
#define SEQ   2048
#define HID   4096
#define NH    32
#define NKV   8
#define DH    128
#define QDIM  (NH * DH)    // 4096
#define KVDIM (NKV * DH)   // 1024

// Scratch (device globals; allocation is forbidden)
__device__ float g_q [SEQ * QDIM];
__device__ float g_k [SEQ * KVDIM];
__device__ float g_v [SEQ * KVDIM];
__device__ __nv_bfloat16 g_hh [SEQ * HID];
__device__ __nv_bfloat16 g_hl [SEQ * HID];
__device__ __nv_bfloat16 g_wqh[QDIM * HID];
__device__ __nv_bfloat16 g_wql[QDIM * HID];
__device__ __nv_bfloat16 g_wkh[KVDIM * HID];
__device__ __nv_bfloat16 g_wkl[KVDIM * HID];
__device__ __nv_bfloat16 g_wvh[KVDIM * HID];
__device__ __nv_bfloat16 g_wvl[KVDIM * HID];
__device__ __nv_bfloat16 g_woh[QDIM * QDIM];
__device__ __nv_bfloat16 g_wol[QDIM * QDIM];
__device__ __nv_bfloat16 g_qh [SEQ * QDIM];
__device__ __nv_bfloat16 g_ql [SEQ * QDIM];
__device__ __nv_bfloat16 g_kh [SEQ * KVDIM];
__device__ __nv_bfloat16 g_kl [SEQ * KVDIM];
__device__ __nv_bfloat16 g_vh [SEQ * KVDIM];
__device__ __nv_bfloat16 g_vl [SEQ * KVDIM];
__device__ __nv_bfloat16 g_aoh[SEQ * QDIM];
__device__ __nv_bfloat16 g_aol[SEQ * QDIM];

// ---------------------------------------------------------------------------
// Helpers
// ---------------------------------------------------------------------------
__device__ __forceinline__ uint32_t smem_u32(const void* p) {
    uint32_t a;
    asm("{ .reg .u64 t; cvta.to.shared.u64 t, %1; cvt.u32.u64 %0, t; }"
        : "=r"(a) : "l"(p));
    return a;
}

#define LDM4(r, addr)                                                         \
    asm volatile("ldmatrix.sync.aligned.m8n8.x4.shared.b16 {%0,%1,%2,%3}, [%4];" \
                 : "=r"((r)[0]), "=r"((r)[1]), "=r"((r)[2]), "=r"((r)[3])     \
                 : "r"(addr))
#define LDM4T(r, addr)                                                        \
    asm volatile("ldmatrix.sync.aligned.m8n8.x4.trans.shared.b16 {%0,%1,%2,%3}, [%4];" \
                 : "=r"((r)[0]), "=r"((r)[1]), "=r"((r)[2]), "=r"((r)[3])     \
                 : "r"(addr))

__device__ __forceinline__ void mma_bf16(float* c, const uint32_t* a,
                                         const uint32_t* b) {
    asm volatile(
        "mma.sync.aligned.m16n8k16.row.col.f32.bf16.bf16.f32 "
        "{%0,%1,%2,%3}, {%4,%5,%6,%7}, {%8,%9}, {%0,%1,%2,%3};"
        : "+f"(c[0]), "+f"(c[1]), "+f"(c[2]), "+f"(c[3])
        : "r"(a[0]), "r"(a[1]), "r"(a[2]), "r"(a[3]), "r"(b[0]), "r"(b[1]));
}

__device__ __forceinline__ uint32_t pack_bf16x2(__nv_bfloat16 a, __nv_bfloat16 b) {
    return (uint32_t)__bfloat16_as_ushort(a) |
           ((uint32_t)__bfloat16_as_ushort(b) << 16);
}

__device__ __forceinline__ void pack2_split(float a, float b,
                                            uint32_t& hi, uint32_t& lo) {
    __nv_bfloat16 ha = __float2bfloat16(a), hb = __float2bfloat16(b);
    hi = pack_bf16x2(ha, hb);
    lo = pack_bf16x2(__float2bfloat16(a - __bfloat162float(ha)),
                     __float2bfloat16(b - __bfloat162float(hb)));
}

// ---------------------------------------------------------------------------
// Elementwise fp32 -> bf16 hi/lo split
// ---------------------------------------------------------------------------
__global__ void split_f32(const float* __restrict__ X,
                          __nv_bfloat16* __restrict__ Xh,
                          __nv_bfloat16* __restrict__ Xl, int n)
{
    int idx = blockIdx.x * blockDim.x + threadIdx.x;
    if (idx >= n) return;
    float x = X[idx];
    __nv_bfloat16 h = __float2bfloat16(x);
    Xh[idx] = h;
    Xl[idx] = __float2bfloat16(x - __bfloat162float(h));
}

// ---------------------------------------------------------------------------
// RoPE + bf16 hi/lo split (scale folded in for Q)
// ---------------------------------------------------------------------------
__global__ void rope_split(const float* __restrict__ X,
                           __nv_bfloat16* __restrict__ Xh,
                           __nv_bfloat16* __restrict__ Xl,
                           const float* __restrict__ cosb,
                           const float* __restrict__ sinb,
                           int nheads, float scale)
{
    int idx = blockIdx.x * blockDim.x + threadIdx.x;
    int total = SEQ * nheads * 64;
    if (idx >= total) return;
    int d = idx & 63;
    int h = (idx >> 6) % nheads;
    int s = idx / (nheads * 64);
    float c  = cosb[s * 128 + d];
    float sn = sinb[s * 128 + d];
    size_t base = ((size_t)s * nheads + h) * DH;
    float x0 = X[base + d], x1 = X[base + d + 64];
    float y0 = (x0 * c - x1 * sn) * scale;
    float y1 = (x1 * c + x0 * sn) * scale;
    __nv_bfloat16 h0 = __float2bfloat16(y0);
    __nv_bfloat16 h1 = __float2bfloat16(y1);
    Xh[base + d]      = h0;
    Xh[base + d + 64] = h1;
    Xl[base + d]      = __float2bfloat16(y0 - __bfloat162float(h0));
    Xl[base + d + 64] = __float2bfloat16(y1 - __bfloat162float(h1));
}

// ---------------------------------------------------------------------------
// bf16x3 split GEMM on pre-split operands:
// C[M,N] = (Ah+Al)[M,K] @ (Bh+Bl)[N,K]^T   (3-pass: AhBh + AlBh + AhBl)
// CTA tile 128x128, BK=32, 256 threads, warp tile 32x64 (4x2 warps)
// ---------------------------------------------------------------------------
#define GS 40
#define TILE_HALF (128 * GS)

__global__ __launch_bounds__(256) void gemm_bf16p(
    const __nv_bfloat16* __restrict__ Ah, const __nv_bfloat16* __restrict__ Al,
    const __nv_bfloat16* __restrict__ Bh, const __nv_bfloat16* __restrict__ Bl,
    float* __restrict__ C, int M, int N, int K)
{
    __shared__ __align__(16) uint16_t sm[4 * TILE_HALF];  // Ah, Al, Bh, Bl

    const int tid = threadIdx.x;
    const int wid = tid >> 5;
    const int lid = tid & 31;
    const int wm  = wid & 3;
    const int wn  = wid >> 2;
    const int bm  = blockIdx.y * 128;
    const int bn  = blockIdx.x * 128;

    const uint32_t sAh = smem_u32(sm);
    const uint32_t sAl = sAh + TILE_HALF * 2;
    const uint32_t sBh = sAh + 2 * TILE_HALF * 2;
    const uint32_t sBl = sAh + 3 * TILE_HALF * 2;

    const int mm = lid >> 3, lr = lid & 7;
    const int a_row = ((mm & 1) << 3) + lr;
    const int a_k   = (mm >> 1) << 3;
    const int b_row = ((mm >> 1) << 3) + lr;
    const int b_k   = (mm & 1) << 3;

    // Load geometry: 2 uint4 (16 bf16) per half-matrix per thread per chunk
    size_t goA[2], goB[2];
    uint32_t so2[2];
    #pragma unroll
    for (int j = 0; j < 2; j++) {
        int f = tid + j * 256;       // 0..511 uint4 slots per half
        int r = f >> 2, c8 = f & 3;  // row 0..127, 8-elem col 0..3
        goA[j] = (size_t)(bm + r) * K + c8 * 8;
        goB[j] = (size_t)(bn + r) * K + c8 * 8;
        so2[j] = r * GS + c8 * 8;
    }

    const int NCH = K / 32;
    uint4 cAh[2], cAl[2], cBh[2], cBl[2];
    #pragma unroll
    for (int j = 0; j < 2; j++) {
        cAh[j] = *(const uint4*)(Ah + goA[j]);
        cAl[j] = *(const uint4*)(Al + goA[j]);
        cBh[j] = *(const uint4*)(Bh + goB[j]);
        cBl[j] = *(const uint4*)(Bl + goB[j]);
    }

    float acc[2][8][4];
    #pragma unroll
    for (int i = 0; i < 2; i++)
        #pragma unroll
        for (int j = 0; j < 8; j++)
            #pragma unroll
            for (int t = 0; t < 4; t++) acc[i][j][t] = 0.f;

    for (int ch = 0; ch < NCH; ch++) {
        #pragma unroll
        for (int j = 0; j < 2; j++) {
            *(uint4*)((uint16_t*)sm + so2[j])                 = cAh[j];
            *(uint4*)((uint16_t*)sm + TILE_HALF + so2[j])     = cAl[j];
            *(uint4*)((uint16_t*)sm + 2*TILE_HALF + so2[j])   = cBh[j];
            *(uint4*)((uint16_t*)sm + 3*TILE_HALF + so2[j])   = cBl[j];
        }
        __syncthreads();

        if (ch + 1 < NCH) {
            #pragma unroll
            for (int j = 0; j < 2; j++) {
                cAh[j] = *(const uint4*)(Ah + goA[j] + (ch + 1) * 32);
                cAl[j] = *(const uint4*)(Al + goA[j] + (ch + 1) * 32);
                cBh[j] = *(const uint4*)(Bh + goB[j] + (ch + 1) * 32);
                cBl[j] = *(const uint4*)(Bl + goB[j] + (ch + 1) * 32);
            }
        }

        #pragma unroll
        for (int kk = 0; kk < 32; kk += 16) {
            uint32_t ah[2][4], al[2][4], bb[4][4];
            uint32_t boff[4];
            #pragma unroll
            for (int i = 0; i < 2; i++) {
                uint32_t off = ((wm*32 + i*16 + a_row) * GS + kk + a_k) * 2;
                LDM4(ah[i], sAh + off);
                LDM4(al[i], sAl + off);
            }
            #pragma unroll
            for (int j = 0; j < 4; j++) {
                boff[j] = ((wn*64 + j*16 + b_row) * GS + kk + b_k) * 2;
                LDM4(bb[j], sBh + boff[j]);
            }
            #pragma unroll
            for (int i = 0; i < 2; i++)
                #pragma unroll
                for (int j = 0; j < 8; j++)
                    mma_bf16(acc[i][j], ah[i], &bb[j>>1][(j&1)*2]);
            #pragma unroll
            for (int i = 0; i < 2; i++)
                #pragma unroll
                for (int j = 0; j < 8; j++)
                    mma_bf16(acc[i][j], al[i], &bb[j>>1][(j&1)*2]);
            #pragma unroll
            for (int j = 0; j < 4; j++) LDM4(bb[j], sBl + boff[j]);
            #pragma unroll
            for (int i = 0; i < 2; i++)
                #pragma unroll
                for (int j = 0; j < 8; j++)
                    mma_bf16(acc[i][j], ah[i], &bb[j>>1][(j&1)*2]);
        }
        __syncthreads();
    }

    const int r0 = bm + wm*32 + (lid >> 2);
    const int c0 = bn + wn*64 + (lid & 3) * 2;
    #pragma unroll
    for (int i = 0; i < 2; i++)
        #pragma unroll
        for (int j = 0; j < 8; j++) {
            int r = r0 + i*16, c = c0 + j*8;
            *(float2*)&C[(size_t)r * N + c]       = make_float2(acc[i][j][0], acc[i][j][1]);
            *(float2*)&C[(size_t)(r+8) * N + c]   = make_float2(acc[i][j][2], acc[i][j][3]);
        }
}

// ---------------------------------------------------------------------------
// Flash attention v2: in-register softmax, P stays in fragments (FA2 style).
// CTA: 128 q-rows x one head, 256 threads; each warp owns 16 q-rows x all cols.
// Causal, GQA (kv head = qhead>>2). Q pre-scaled by 1/sqrt(D).
// Output written pre-split to bf16 hi/lo.
// ---------------------------------------------------------------------------
#define FQT 128
#define FKT 64
#define FS2 136
#define FOFF_QH 0
#define FOFF_QL (FOFF_QH + FQT*FS2*2)
#define FOFF_KH (FOFF_QL + FQT*FS2*2)
#define FOFF_KL (FOFF_KH + FKT*FS2*2)
#define FOFF_VH (FOFF_KL + FKT*FS2*2)
#define FOFF_VL (FOFF_VH + FKT*FS2*2)
#define FLASH3_SMEM (FOFF_VL + FKT*FS2*2)

__global__ __launch_bounds__(256, 1) void flash_reg(
    const __nv_bfloat16* __restrict__ Qh, const __nv_bfloat16* __restrict__ Ql,
    const __nv_bfloat16* __restrict__ Kh, const __nv_bfloat16* __restrict__ Kl,
    const __nv_bfloat16* __restrict__ Vh, const __nv_bfloat16* __restrict__ Vl,
    __nv_bfloat16* __restrict__ Oh, __nv_bfloat16* __restrict__ Ol)
{
    extern __shared__ char fsm[];
    const uint32_t sb = smem_u32(fsm);
    __nv_bfloat16* sQh = (__nv_bfloat16*)(fsm + FOFF_QH);
    __nv_bfloat16* sQl = (__nv_bfloat16*)(fsm + FOFF_QL);
    __nv_bfloat16* sKh = (__nv_bfloat16*)(fsm + FOFF_KH);
    __nv_bfloat16* sKl = (__nv_bfloat16*)(fsm + FOFF_KL);
    __nv_bfloat16* sVh = (__nv_bfloat16*)(fsm + FOFF_VH);
    __nv_bfloat16* sVl = (__nv_bfloat16*)(fsm + FOFF_VL);

    const int tid = threadIdx.x;
    const int wid = tid >> 5;
    const int lid = tid & 31;
    const int g   = lid >> 2;
    const int t   = lid & 3;
    const int qb  = gridDim.x - 1 - blockIdx.x;   // heavy tiles first
    const int h   = blockIdx.y;
    const int kvh = h >> 2;
    const int q0  = qb * FQT;
    const int wr0 = wid * 16;                     // warp's q-row base (local)

    const int mm = lid >> 3, lr = lid & 7;
    const int a_row = ((mm & 1) << 3) + lr;
    const int a_k   = (mm >> 1) << 3;
    const int b_row = ((mm >> 1) << 3) + lr;
    const int b_k   = (mm & 1) << 3;
    const int v_k   = ((mm & 1) << 3) + lr;
    const int v_n   = (mm >> 1) << 3;

    // Load Q tile (128 x 128, hi+lo)
    for (int i = tid; i < FQT * 16; i += 256) {
        int r = i >> 4, c8 = i & 15;
        size_t gb = ((size_t)(q0 + r) * NH + h) * DH + c8 * 8;
        *(uint4*)(sQh + r * FS2 + c8 * 8) = *(const uint4*)(Qh + gb);
        *(uint4*)(sQl + r * FS2 + c8 * 8) = *(const uint4*)(Ql + gb);
    }

    float m0 = -1e30f, m1 = -1e30f, l0 = 0.f, l1 = 0.f;
    float oacc[16][4];
    #pragma unroll
    for (int j = 0; j < 16; j++)
        #pragma unroll
        for (int e = 0; e < 4; e++) oacc[j][e] = 0.f;

    const int ntiles = 2 * qb + 2;
    for (int kt = 0; kt < ntiles; kt++) {
        const int k0 = kt * FKT;
        // Load K,V tiles (64 x 128, hi+lo)
        for (int i = tid; i < FKT * 16; i += 256) {
            int r = i >> 4, c8 = i & 15;
            size_t gb = ((size_t)(k0 + r) * NKV + kvh) * DH + c8 * 8;
            *(uint4*)(sKh + r * FS2 + c8 * 8) = *(const uint4*)(Kh + gb);
            *(uint4*)(sKl + r * FS2 + c8 * 8) = *(const uint4*)(Kl + gb);
            *(uint4*)(sVh + r * FS2 + c8 * 8) = *(const uint4*)(Vh + gb);
            *(uint4*)(sVl + r * FS2 + c8 * 8) = *(const uint4*)(Vl + gb);
        }
        __syncthreads();

        // ---- S = Q @ K^T : warp tile 16x64, 3-pass split ----
        float sacc[8][4];
        #pragma unroll
        for (int j = 0; j < 8; j++)
            #pragma unroll
            for (int e = 0; e < 4; e++) sacc[j][e] = 0.f;

        #pragma unroll
        for (int kk = 0; kk < 8; kk++) {
            uint32_t qh_[4], ql_[4], kf[4][4];
            uint32_t boff[4];
            uint32_t aoff = (uint32_t)((wr0 + a_row) * FS2 + kk*16 + a_k) * 2;
            LDM4(qh_, sb + FOFF_QH + aoff);
            LDM4(ql_, sb + FOFF_QL + aoff);
            #pragma unroll
            for (int n = 0; n < 4; n++) {
                boff[n] = (uint32_t)((n*16 + b_row) * FS2 + kk*16 + b_k) * 2;
                LDM4(kf[n], sb + FOFF_KH + boff[n]);
            }
            #pragma unroll
            for (int nf = 0; nf < 8; nf++) mma_bf16(sacc[nf], qh_, &kf[nf>>1][(nf&1)*2]);
            #pragma unroll
            for (int nf = 0; nf < 8; nf++) mma_bf16(sacc[nf], ql_, &kf[nf>>1][(nf&1)*2]);
            #pragma unroll
            for (int n = 0; n < 4; n++) LDM4(kf[n], sb + FOFF_KL + boff[n]);
            #pragma unroll
            for (int nf = 0; nf < 8; nf++) mma_bf16(sacc[nf], qh_, &kf[nf>>1][(nf&1)*2]);
        }

        // ---- causal mask (diagonal tiles only) ----
        if (kt >= 2 * qb) {
            int row0 = q0 + wr0 + g;
            #pragma unroll
            for (int nf = 0; nf < 8; nf++) {
                int col = k0 + nf*8 + t*2;
                if (col     > row0)     sacc[nf][0] = -1e30f;
                if (col + 1 > row0)     sacc[nf][1] = -1e30f;
                if (col     > row0 + 8) sacc[nf][2] = -1e30f;
                if (col + 1 > row0 + 8) sacc[nf][3] = -1e30f;
            }
        }

        // ---- in-register online softmax ----
        float tm0 = -1e30f, tm1 = -1e30f;
        #pragma unroll
        for (int nf = 0; nf < 8; nf++) {
            tm0 = fmaxf(tm0, fmaxf(sacc[nf][0], sacc[nf][1]));
            tm1 = fmaxf(tm1, fmaxf(sacc[nf][2], sacc[nf][3]));
        }
        tm0 = fmaxf(tm0, __shfl_xor_sync(0xffffffffu, tm0, 1));
        tm0 = fmaxf(tm0, __shfl_xor_sync(0xffffffffu, tm0, 2));
        tm1 = fmaxf(tm1, __shfl_xor_sync(0xffffffffu, tm1, 1));
        tm1 = fmaxf(tm1, __shfl_xor_sync(0xffffffffu, tm1, 2));
        float nm0 = fmaxf(m0, tm0), nm1 = fmaxf(m1, tm1);
        float c0 = __expf(m0 - nm0), c1 = __expf(m1 - nm1);
        m0 = nm0; m1 = nm1;

        float rs0 = 0.f, rs1 = 0.f;
        #pragma unroll
        for (int nf = 0; nf < 8; nf++) {
            float p0 = __expf(sacc[nf][0] - m0);
            float p1 = __expf(sacc[nf][1] - m0);
            float p2 = __expf(sacc[nf][2] - m1);
            float p3 = __expf(sacc[nf][3] - m1);
            sacc[nf][0] = p0; sacc[nf][1] = p1; sacc[nf][2] = p2; sacc[nf][3] = p3;
            rs0 += p0 + p1; rs1 += p2 + p3;
        }
        rs0 += __shfl_xor_sync(0xffffffffu, rs0, 1);
        rs0 += __shfl_xor_sync(0xffffffffu, rs0, 2);
        rs1 += __shfl_xor_sync(0xffffffffu, rs1, 1);
        rs1 += __shfl_xor_sync(0xffffffffu, rs1, 2);
        l0 = l0 * c0 + rs0;
        l1 = l1 * c1 + rs1;

        #pragma unroll
        for (int j = 0; j < 16; j++) {
            oacc[j][0] *= c0; oacc[j][1] *= c0;
            oacc[j][2] *= c1; oacc[j][3] *= c1;
        }

        // ---- repack P fragments (C->A layout identity), hi/lo split ----
        uint32_t ph[4][4], pl[4][4];
        #pragma unroll
        for (int kb = 0; kb < 4; kb++) {
            int f0 = 2*kb, f1 = 2*kb + 1;
            pack2_split(sacc[f0][0], sacc[f0][1], ph[kb][0], pl[kb][0]);
            pack2_split(sacc[f0][2], sacc[f0][3], ph[kb][1], pl[kb][1]);
            pack2_split(sacc[f1][0], sacc[f1][1], ph[kb][2], pl[kb][2]);
            pack2_split(sacc[f1][2], sacc[f1][3], ph[kb][3], pl[kb][3]);
        }

        // ---- O += P @ V : warp tile 16x128, 3-pass split ----
        #pragma unroll
        for (int kb = 0; kb < 4; kb++) {
            #pragma unroll
            for (int half = 0; half < 2; half++) {
                uint32_t vv[4][4], voff[4];
                #pragma unroll
                for (int n = 0; n < 4; n++) {
                    voff[n] = (uint32_t)((kb*16 + v_k) * FS2 + (half*4 + n)*16 + v_n) * 2;
                    LDM4T(vv[n], sb + FOFF_VH + voff[n]);
                }
                #pragma unroll
                for (int j = 0; j < 8; j++)
                    mma_bf16(oacc[half*8 + j], ph[kb], &vv[j>>1][(j&1)*2]);
                #pragma unroll
                for (int j = 0; j < 8; j++)
                    mma_bf16(oacc[half*8 + j], pl[kb], &vv[j>>1][(j&1)*2]);
                #pragma unroll
                for (int n = 0; n < 4; n++) LDM4T(vv[n], sb + FOFF_VL + voff[n]);
                #pragma unroll
                for (int j = 0; j < 8; j++)
                    mma_bf16(oacc[half*8 + j], ph[kb], &vv[j>>1][(j&1)*2]);
            }
        }
        __syncthreads();   // before next tile overwrites K/V smem
    }

    // ---- epilogue: normalize, split to bf16 hi/lo, store ----
    {
        float inv0 = 1.0f / l0;
        float inv1 = 1.0f / l1;
        int gr0 = q0 + wr0 + g;
        #pragma unroll
        for (int j = 0; j < 16; j++) {
            int gc = j*8 + t*2;
            uint32_t hi, lo;
            pack2_split(oacc[j][0]*inv0, oacc[j][1]*inv0, hi, lo);
            size_t o0 = ((size_t)gr0 * NH + h) * DH + gc;
            *(uint32_t*)&Oh[o0] = hi;
            *(uint32_t*)&Ol[o0] = lo;
            pack2_split(oacc[j][2]*inv1, oacc[j][3]*inv1, hi, lo);
            size_t o1 = ((size_t)(gr0 + 8) * NH + h) * DH + gc;
            *(uint32_t*)&Oh[o1] = hi;
            *(uint32_t*)&Ol[o1] = lo;
        }
    }
}

// ---------------------------------------------------------------------------
// Launch
// ---------------------------------------------------------------------------
extern "C" void kernel_launch(void* const* d_in, const int* in_sizes, int n_in,
                              void* d_out, int out_size)
{
    const float* hidden = (const float*)d_in[0];
    const float* cosb   = (const float*)d_in[1];
    const float* sinb   = (const float*)d_in[2];
    // d_in[3] = attention_mask (pure causal; applied analytically)
    const float* Wq     = (const float*)d_in[4];
    const float* Wk     = (const float*)d_in[5];
    const float* Wv     = (const float*)d_in[6];
    const float* Wo     = (const float*)d_in[7];
    float* out = (float*)d_out;

    float *qp, *kp, *vp;
    cudaGetSymbolAddress((void**)&qp, g_q);
    cudaGetSymbolAddress((void**)&kp, g_k);
    cudaGetSymbolAddress((void**)&vp, g_v);
    __nv_bfloat16 *hh, *hl, *wqh, *wql, *wkh, *wkl, *wvh, *wvl, *woh, *wol;
    __nv_bfloat16 *qh, *ql, *kh, *kl, *vh, *vl, *aoh, *aol;
    cudaGetSymbolAddress((void**)&hh,  g_hh);
    cudaGetSymbolAddress((void**)&hl,  g_hl);
    cudaGetSymbolAddress((void**)&wqh, g_wqh);
    cudaGetSymbolAddress((void**)&wql, g_wql);
    cudaGetSymbolAddress((void**)&wkh, g_wkh);
    cudaGetSymbolAddress((void**)&wkl, g_wkl);
    cudaGetSymbolAddress((void**)&wvh, g_wvh);
    cudaGetSymbolAddress((void**)&wvl, g_wvl);
    cudaGetSymbolAddress((void**)&woh, g_woh);
    cudaGetSymbolAddress((void**)&wol, g_wol);
    cudaGetSymbolAddress((void**)&qh,  g_qh);
    cudaGetSymbolAddress((void**)&ql,  g_ql);
    cudaGetSymbolAddress((void**)&kh,  g_kh);
    cudaGetSymbolAddress((void**)&kl,  g_kl);
    cudaGetSymbolAddress((void**)&vh,  g_vh);
    cudaGetSymbolAddress((void**)&vl,  g_vl);
    cudaGetSymbolAddress((void**)&aoh, g_aoh);
    cudaGetSymbolAddress((void**)&aol, g_aol);

    cudaFuncSetAttribute(flash_reg, cudaFuncAttributeMaxDynamicSharedMemorySize,
                         FLASH3_SMEM);

    // Pre-split operands to bf16 hi/lo
    split_f32<<<(SEQ*HID + 255)/256, 256>>>(hidden, hh, hl, SEQ*HID);
    split_f32<<<(QDIM*HID + 255)/256, 256>>>(Wq, wqh, wql, QDIM*HID);
    split_f32<<<(KVDIM*HID + 255)/256, 256>>>(Wk, wkh, wkl, KVDIM*HID);
    split_f32<<<(KVDIM*HID + 255)/256, 256>>>(Wv, wvh, wvl, KVDIM*HID);
    split_f32<<<(QDIM*QDIM + 255)/256, 256>>>(Wo, woh, wol, QDIM*QDIM);

    // Projections (tensor cores via mma.sync, bf16 split x3)
    gemm_bf16p<<<dim3(QDIM/128,  SEQ/128), 256>>>(hh, hl, wqh, wql, qp, SEQ, QDIM,  HID);
    gemm_bf16p<<<dim3(KVDIM/128, SEQ/128), 256>>>(hh, hl, wkh, wkl, kp, SEQ, KVDIM, HID);
    gemm_bf16p<<<dim3(KVDIM/128, SEQ/128), 256>>>(hh, hl, wvh, wvl, vp, SEQ, KVDIM, HID);

    // RoPE + bf16 split (Q also gets 1/sqrt(D) folded in)
    const float scale = 0.08838834764831845f;   // 128^-0.5
    rope_split<<<(SEQ*NH*64 + 255)/256, 256>>>(qp, qh, ql, cosb, sinb, NH,  scale);
    rope_split<<<(SEQ*NKV*64 + 255)/256, 256>>>(kp, kh, kl, cosb, sinb, NKV, 1.0f);
    split_f32<<<(SEQ*KVDIM + 255)/256, 256>>>(vp, vh, vl, SEQ*KVDIM);

    // Flash attention (in-register softmax, tensor cores)
    flash_reg<<<dim3(SEQ/FQT, NH), 256, FLASH3_SMEM>>>(qh, ql, kh, kl, vh, vl, aoh, aol);

    // Output projection
    gemm_bf16p<<<dim3(QDIM/128, SEQ/128), 256>>>(aoh, aol, woh, wol, out, SEQ, QDIM, HID);
}

// round 7
// speedup vs baseline: 3.3112x; 1.0950x over previous
#include <cuda_runtime.h>
#include <cuda_bf16.h>
#include <cstdint>
#include <math.h>

// Problem constants
#define SEQ   2048
#define HID   4096
#define NH    32
#define NKV   8
#define DH    128
#define QDIM  (NH * DH)    // 4096
#define KVDIM (NKV * DH)   // 1024

// Scratch (device globals; allocation is forbidden)
__device__ float g_q [SEQ * QDIM];
__device__ float g_k [SEQ * KVDIM];
__device__ float g_v [SEQ * KVDIM];
__device__ __nv_bfloat16 g_hh [SEQ * HID];
__device__ __nv_bfloat16 g_hl [SEQ * HID];
__device__ __nv_bfloat16 g_wqh[QDIM * HID];
__device__ __nv_bfloat16 g_wql[QDIM * HID];
__device__ __nv_bfloat16 g_wkh[KVDIM * HID];
__device__ __nv_bfloat16 g_wkl[KVDIM * HID];
__device__ __nv_bfloat16 g_wvh[KVDIM * HID];
__device__ __nv_bfloat16 g_wvl[KVDIM * HID];
__device__ __nv_bfloat16 g_woh[QDIM * QDIM];
__device__ __nv_bfloat16 g_wol[QDIM * QDIM];
__device__ __nv_bfloat16 g_qh [SEQ * QDIM];
__device__ __nv_bfloat16 g_ql [SEQ * QDIM];
__device__ __nv_bfloat16 g_kh [SEQ * KVDIM];
__device__ __nv_bfloat16 g_kl [SEQ * KVDIM];
__device__ __nv_bfloat16 g_vh [SEQ * KVDIM];
__device__ __nv_bfloat16 g_vl [SEQ * KVDIM];
__device__ __nv_bfloat16 g_aoh[SEQ * QDIM];
__device__ __nv_bfloat16 g_aol[SEQ * QDIM];

// ---------------------------------------------------------------------------
// Helpers
// ---------------------------------------------------------------------------
__device__ __forceinline__ uint32_t smem_u32(const void* p) {
    uint32_t a;
    asm("{ .reg .u64 t; cvta.to.shared.u64 t, %1; cvt.u32.u64 %0, t; }"
        : "=r"(a) : "l"(p));
    return a;
}

#define LDM4(r, addr)                                                         \
    asm volatile("ldmatrix.sync.aligned.m8n8.x4.shared.b16 {%0,%1,%2,%3}, [%4];" \
                 : "=r"((r)[0]), "=r"((r)[1]), "=r"((r)[2]), "=r"((r)[3])     \
                 : "r"(addr))
#define LDM4T(r, addr)                                                        \
    asm volatile("ldmatrix.sync.aligned.m8n8.x4.trans.shared.b16 {%0,%1,%2,%3}, [%4];" \
                 : "=r"((r)[0]), "=r"((r)[1]), "=r"((r)[2]), "=r"((r)[3])     \
                 : "r"(addr))

__device__ __forceinline__ void mma_bf16(float* c, const uint32_t* a,
                                         const uint32_t* b) {
    asm volatile(
        "mma.sync.aligned.m16n8k16.row.col.f32.bf16.bf16.f32 "
        "{%0,%1,%2,%3}, {%4,%5,%6,%7}, {%8,%9}, {%0,%1,%2,%3};"
        : "+f"(c[0]), "+f"(c[1]), "+f"(c[2]), "+f"(c[3])
        : "r"(a[0]), "r"(a[1]), "r"(a[2]), "r"(a[3]), "r"(b[0]), "r"(b[1]));
}

__device__ __forceinline__ void cp16(uint32_t s, const void* g) {
    asm volatile("cp.async.cg.shared.global [%0], [%1], 16;"
                 :: "r"(s), "l"(g));
}
__device__ __forceinline__ void cp_commit() {
    asm volatile("cp.async.commit_group;");
}
template<int N> __device__ __forceinline__ void cp_wait() {
    asm volatile("cp.async.wait_group %0;" :: "n"(N));
}

__device__ __forceinline__ uint32_t pack_bf16x2(__nv_bfloat16 a, __nv_bfloat16 b) {
    return (uint32_t)__bfloat16_as_ushort(a) |
           ((uint32_t)__bfloat16_as_ushort(b) << 16);
}

__device__ __forceinline__ void pack2_split(float a, float b,
                                            uint32_t& hi, uint32_t& lo) {
    __nv_bfloat16 ha = __float2bfloat16(a), hb = __float2bfloat16(b);
    hi = pack_bf16x2(ha, hb);
    lo = pack_bf16x2(__float2bfloat16(a - __bfloat162float(ha)),
                     __float2bfloat16(b - __bfloat162float(hb)));
}

// ---------------------------------------------------------------------------
// Elementwise fp32 -> bf16 hi/lo split (vectorized x4)
// ---------------------------------------------------------------------------
__global__ void split_f32(const float* __restrict__ X,
                          __nv_bfloat16* __restrict__ Xh,
                          __nv_bfloat16* __restrict__ Xl, int n4)
{
    int idx = blockIdx.x * blockDim.x + threadIdx.x;
    if (idx >= n4) return;
    float4 x = *(const float4*)(X + idx * 4);
    uint32_t h0, l0, h1, l1;
    pack2_split(x.x, x.y, h0, l0);
    pack2_split(x.z, x.w, h1, l1);
    *(uint2*)(Xh + idx * 4) = make_uint2(h0, h1);
    *(uint2*)(Xl + idx * 4) = make_uint2(l0, l1);
}

// ---------------------------------------------------------------------------
// RoPE + bf16 hi/lo split (scale folded in for Q), vectorized x2
// ---------------------------------------------------------------------------
__global__ void rope_split(const float* __restrict__ X,
                           __nv_bfloat16* __restrict__ Xh,
                           __nv_bfloat16* __restrict__ Xl,
                           const float* __restrict__ cosb,
                           const float* __restrict__ sinb,
                           int nheads, float scale)
{
    int idx = blockIdx.x * blockDim.x + threadIdx.x;
    int total = SEQ * nheads * 32;
    if (idx >= total) return;
    int d = (idx & 31) * 2;
    int h = (idx >> 5) % nheads;
    int s = idx / (nheads * 32);
    float2 c  = *(const float2*)(cosb + s * 128 + d);
    float2 sn = *(const float2*)(sinb + s * 128 + d);
    size_t base = ((size_t)s * nheads + h) * DH;
    float2 x0 = *(const float2*)(X + base + d);
    float2 x1 = *(const float2*)(X + base + d + 64);
    float y0a = (x0.x * c.x - x1.x * sn.x) * scale;
    float y0b = (x0.y * c.y - x1.y * sn.y) * scale;
    float y1a = (x1.x * c.x + x0.x * sn.x) * scale;
    float y1b = (x1.y * c.y + x0.y * sn.y) * scale;
    uint32_t h0, l0, h1, l1;
    pack2_split(y0a, y0b, h0, l0);
    pack2_split(y1a, y1b, h1, l1);
    *(uint32_t*)(Xh + base + d)      = h0;
    *(uint32_t*)(Xl + base + d)      = l0;
    *(uint32_t*)(Xh + base + d + 64) = h1;
    *(uint32_t*)(Xl + base + d + 64) = l1;
}

// ---------------------------------------------------------------------------
// bf16x3 split GEMM, cp.async 2-stage double buffer.
// C[M,N] = (Ah+Al)[M,K] @ (Bh+Bl)[N,K]^T   (3-pass: AhBh + AlBh + AhBl)
// CTA tile 128x128, BK=32, 256 threads, warp tile 32x64 (4x2 warps).
// Optional second output: blocks with blockIdx.x >= nsplit use B2/C2.
// ---------------------------------------------------------------------------
#define GS 40
#define GST (128 * GS)                 // elems per half per stage
#define GSTAGE_B (4 * GST * 2)         // stage bytes (40960)
#define GEMM_SMEM_B (2 * GSTAGE_B)     // 81920

__global__ __launch_bounds__(256) void gemm_cp(
    const __nv_bfloat16* __restrict__ Ah, const __nv_bfloat16* __restrict__ Al,
    const __nv_bfloat16* __restrict__ Bh_, const __nv_bfloat16* __restrict__ Bl_,
    float* __restrict__ C_,
    const __nv_bfloat16* __restrict__ B2h, const __nv_bfloat16* __restrict__ B2l,
    float* __restrict__ C2, int nsplit, int M, int N, int K)
{
    extern __shared__ __align__(16) uint16_t dsm[];
    const uint32_t sb = smem_u32(dsm);

    const __nv_bfloat16* Bh = Bh_;
    const __nv_bfloat16* Bl = Bl_;
    float* C = C_;
    int bx = blockIdx.x;
    if (bx >= nsplit) { Bh = B2h; Bl = B2l; C = C2; bx -= nsplit; }

    const int tid = threadIdx.x;
    const int wid = tid >> 5;
    const int lid = tid & 31;
    const int wm  = wid & 3;
    const int wn  = wid >> 2;
    const int bm  = blockIdx.y * 128;
    const int bn  = bx * 128;

    const int mm = lid >> 3, lr = lid & 7;
    const int a_row = ((mm & 1) << 3) + lr;
    const int a_k   = (mm >> 1) << 3;
    const int b_row = ((mm >> 1) << 3) + lr;
    const int b_k   = (mm & 1) << 3;

    // copy geometry: 2 uint4 (16B) per half per thread per chunk
    size_t goA[2], goB[2];
    uint32_t soB[2];               // byte offset within a half
    #pragma unroll
    for (int j = 0; j < 2; j++) {
        int f = tid + j * 256;     // 0..511
        int r = f >> 2, c8 = f & 3;
        goA[j] = (size_t)(bm + r) * K + c8 * 8;
        goB[j] = (size_t)(bn + r) * K + c8 * 8;
        soB[j] = (uint32_t)(r * GS + c8 * 8) * 2;
    }

    const int NCH = K / 32;

    // issue chunk ch into stage s
    auto issue = [&](int ch, int s) {
        uint32_t st = sb + s * GSTAGE_B;
        #pragma unroll
        for (int j = 0; j < 2; j++) {
            cp16(st + 0*GST*2 + soB[j], Ah + goA[j] + ch * 32);
            cp16(st + 1*GST*2 + soB[j], Al + goA[j] + ch * 32);
            cp16(st + 2*GST*2 + soB[j], Bh + goB[j] + ch * 32);
            cp16(st + 3*GST*2 + soB[j], Bl + goB[j] + ch * 32);
        }
        cp_commit();
    };

    issue(0, 0);

    float acc[2][8][4];
    #pragma unroll
    for (int i = 0; i < 2; i++)
        #pragma unroll
        for (int j = 0; j < 8; j++)
            #pragma unroll
            for (int t = 0; t < 4; t++) acc[i][j][t] = 0.f;

    for (int ch = 0; ch < NCH; ch++) {
        const int s = ch & 1;
        if (ch + 1 < NCH) { issue(ch + 1, s ^ 1); cp_wait<1>(); }
        else              { cp_wait<0>(); }
        __syncthreads();

        const uint32_t sAh = sb + s * GSTAGE_B;
        const uint32_t sAl = sAh + GST * 2;
        const uint32_t sBh = sAh + 2 * GST * 2;
        const uint32_t sBl = sAh + 3 * GST * 2;

        #pragma unroll
        for (int kk = 0; kk < 32; kk += 16) {
            uint32_t ah[2][4], al[2][4], bb[4][4];
            uint32_t boff[4];
            #pragma unroll
            for (int i = 0; i < 2; i++) {
                uint32_t off = ((wm*32 + i*16 + a_row) * GS + kk + a_k) * 2;
                LDM4(ah[i], sAh + off);
                LDM4(al[i], sAl + off);
            }
            #pragma unroll
            for (int j = 0; j < 4; j++) {
                boff[j] = ((wn*64 + j*16 + b_row) * GS + kk + b_k) * 2;
                LDM4(bb[j], sBh + boff[j]);
            }
            #pragma unroll
            for (int i = 0; i < 2; i++)
                #pragma unroll
                for (int j = 0; j < 8; j++)
                    mma_bf16(acc[i][j], ah[i], &bb[j>>1][(j&1)*2]);
            #pragma unroll
            for (int i = 0; i < 2; i++)
                #pragma unroll
                for (int j = 0; j < 8; j++)
                    mma_bf16(acc[i][j], al[i], &bb[j>>1][(j&1)*2]);
            #pragma unroll
            for (int j = 0; j < 4; j++) LDM4(bb[j], sBl + boff[j]);
            #pragma unroll
            for (int i = 0; i < 2; i++)
                #pragma unroll
                for (int j = 0; j < 8; j++)
                    mma_bf16(acc[i][j], ah[i], &bb[j>>1][(j&1)*2]);
        }
        __syncthreads();
    }

    const int r0 = bm + wm*32 + (lid >> 2);
    const int c0 = bn + wn*64 + (lid & 3) * 2;
    #pragma unroll
    for (int i = 0; i < 2; i++)
        #pragma unroll
        for (int j = 0; j < 8; j++) {
            int r = r0 + i*16, c = c0 + j*8;
            *(float2*)&C[(size_t)r * N + c]       = make_float2(acc[i][j][0], acc[i][j][1]);
            *(float2*)&C[(size_t)(r+8) * N + c]   = make_float2(acc[i][j][2], acc[i][j][3]);
        }
}

// ---------------------------------------------------------------------------
// Flash attention: in-register softmax, cp.async 2-stage K/V double buffer.
// CTA: 128 q-rows x one head, 256 threads; warp owns 16 q-rows x all cols.
// Causal, GQA (kv head = qhead>>2). Q pre-scaled by 1/sqrt(D).
// Output written pre-split to bf16 hi/lo.
// ---------------------------------------------------------------------------
#define FQT 128
#define FKT 64
#define FS2 136
#define FQ_BYTES  (FQT * FS2 * 2)          // 34816 per Q half
#define FKV_ARR   (FKT * FS2 * 2)          // 17408 per K/V array
#define FKV_STAGE (4 * FKV_ARR)            // 69632 per stage
#define FOFF_QH 0
#define FOFF_QL FQ_BYTES
#define FOFF_KV (2 * FQ_BYTES)
#define FLASH3_SMEM (FOFF_KV + 2 * FKV_STAGE)   // 208896

__global__ __launch_bounds__(256, 1) void flash_reg(
    const __nv_bfloat16* __restrict__ Qh, const __nv_bfloat16* __restrict__ Ql,
    const __nv_bfloat16* __restrict__ Kh, const __nv_bfloat16* __restrict__ Kl,
    const __nv_bfloat16* __restrict__ Vh, const __nv_bfloat16* __restrict__ Vl,
    __nv_bfloat16* __restrict__ Oh, __nv_bfloat16* __restrict__ Ol)
{
    extern __shared__ char fsm[];
    const uint32_t sb = smem_u32(fsm);
    __nv_bfloat16* sQh = (__nv_bfloat16*)(fsm + FOFF_QH);
    __nv_bfloat16* sQl = (__nv_bfloat16*)(fsm + FOFF_QL);

    const int tid = threadIdx.x;
    const int wid = tid >> 5;
    const int lid = tid & 31;
    const int g   = lid >> 2;
    const int t   = lid & 3;
    const int qb  = gridDim.x - 1 - blockIdx.x;   // heavy tiles first
    const int h   = blockIdx.y;
    const int kvh = h >> 2;
    const int q0  = qb * FQT;
    const int wr0 = wid * 16;

    const int mm = lid >> 3, lr = lid & 7;
    const int a_row = ((mm & 1) << 3) + lr;
    const int a_k   = (mm >> 1) << 3;
    const int b_row = ((mm >> 1) << 3) + lr;
    const int b_k   = (mm & 1) << 3;
    const int v_k   = ((mm & 1) << 3) + lr;
    const int v_n   = (mm >> 1) << 3;

    const int ntiles = 2 * qb + 2;

    // issue K/V tile kt into stage s (16 cp.async per thread)
    auto issue_kv = [&](int kt, int s) {
        uint32_t st = sb + FOFF_KV + s * FKV_STAGE;
        const int k0 = kt * FKT;
        for (int i = tid; i < FKT * 16; i += 256) {
            int r = i >> 4, c8 = i & 15;
            size_t gb = ((size_t)(k0 + r) * NKV + kvh) * DH + c8 * 8;
            uint32_t so = (uint32_t)(r * FS2 + c8 * 8) * 2;
            cp16(st + 0*FKV_ARR + so, Kh + gb);
            cp16(st + 1*FKV_ARR + so, Kl + gb);
            cp16(st + 2*FKV_ARR + so, Vh + gb);
            cp16(st + 3*FKV_ARR + so, Vl + gb);
        }
        cp_commit();
    };

    issue_kv(0, 0);

    // Load Q tile (128 x 128, hi+lo) with regular loads
    for (int i = tid; i < FQT * 16; i += 256) {
        int r = i >> 4, c8 = i & 15;
        size_t gb = ((size_t)(q0 + r) * NH + h) * DH + c8 * 8;
        *(uint4*)(sQh + r * FS2 + c8 * 8) = *(const uint4*)(Qh + gb);
        *(uint4*)(sQl + r * FS2 + c8 * 8) = *(const uint4*)(Ql + gb);
    }

    float m0 = -1e30f, m1 = -1e30f, l0 = 0.f, l1 = 0.f;
    float oacc[16][4];
    #pragma unroll
    for (int j = 0; j < 16; j++)
        #pragma unroll
        for (int e = 0; e < 4; e++) oacc[j][e] = 0.f;

    for (int kt = 0; kt < ntiles; kt++) {
        const int s = kt & 1;
        if (kt + 1 < ntiles) { issue_kv(kt + 1, s ^ 1); cp_wait<1>(); }
        else                 { cp_wait<0>(); }
        __syncthreads();

        const uint32_t sKH = sb + FOFF_KV + s * FKV_STAGE;
        const uint32_t sKL = sKH + FKV_ARR;
        const uint32_t sVH = sKH + 2 * FKV_ARR;
        const uint32_t sVL = sKH + 3 * FKV_ARR;
        const int k0 = kt * FKT;

        // ---- S = Q @ K^T : warp tile 16x64, 3-pass split ----
        float sacc[8][4];
        #pragma unroll
        for (int j = 0; j < 8; j++)
            #pragma unroll
            for (int e = 0; e < 4; e++) sacc[j][e] = 0.f;

        #pragma unroll
        for (int kk = 0; kk < 8; kk++) {
            uint32_t qh_[4], ql_[4], kf[4][4];
            uint32_t boff[4];
            uint32_t aoff = (uint32_t)((wr0 + a_row) * FS2 + kk*16 + a_k) * 2;
            LDM4(qh_, sb + FOFF_QH + aoff);
            LDM4(ql_, sb + FOFF_QL + aoff);
            #pragma unroll
            for (int n = 0; n < 4; n++) {
                boff[n] = (uint32_t)((n*16 + b_row) * FS2 + kk*16 + b_k) * 2;
                LDM4(kf[n], sKH + boff[n]);
            }
            #pragma unroll
            for (int nf = 0; nf < 8; nf++) mma_bf16(sacc[nf], qh_, &kf[nf>>1][(nf&1)*2]);
            #pragma unroll
            for (int nf = 0; nf < 8; nf++) mma_bf16(sacc[nf], ql_, &kf[nf>>1][(nf&1)*2]);
            #pragma unroll
            for (int n = 0; n < 4; n++) LDM4(kf[n], sKL + boff[n]);
            #pragma unroll
            for (int nf = 0; nf < 8; nf++) mma_bf16(sacc[nf], qh_, &kf[nf>>1][(nf&1)*2]);
        }

        // ---- causal mask (diagonal tiles only) ----
        if (kt >= 2 * qb) {
            int row0 = q0 + wr0 + g;
            #pragma unroll
            for (int nf = 0; nf < 8; nf++) {
                int col = k0 + nf*8 + t*2;
                if (col     > row0)     sacc[nf][0] = -1e30f;
                if (col + 1 > row0)     sacc[nf][1] = -1e30f;
                if (col     > row0 + 8) sacc[nf][2] = -1e30f;
                if (col + 1 > row0 + 8) sacc[nf][3] = -1e30f;
            }
        }

        // ---- in-register online softmax ----
        float tm0 = -1e30f, tm1 = -1e30f;
        #pragma unroll
        for (int nf = 0; nf < 8; nf++) {
            tm0 = fmaxf(tm0, fmaxf(sacc[nf][0], sacc[nf][1]));
            tm1 = fmaxf(tm1, fmaxf(sacc[nf][2], sacc[nf][3]));
        }
        tm0 = fmaxf(tm0, __shfl_xor_sync(0xffffffffu, tm0, 1));
        tm0 = fmaxf(tm0, __shfl_xor_sync(0xffffffffu, tm0, 2));
        tm1 = fmaxf(tm1, __shfl_xor_sync(0xffffffffu, tm1, 1));
        tm1 = fmaxf(tm1, __shfl_xor_sync(0xffffffffu, tm1, 2));
        float nm0 = fmaxf(m0, tm0), nm1 = fmaxf(m1, tm1);
        float c0 = __expf(m0 - nm0), c1 = __expf(m1 - nm1);
        m0 = nm0; m1 = nm1;

        float rs0 = 0.f, rs1 = 0.f;
        #pragma unroll
        for (int nf = 0; nf < 8; nf++) {
            float p0 = __expf(sacc[nf][0] - m0);
            float p1 = __expf(sacc[nf][1] - m0);
            float p2 = __expf(sacc[nf][2] - m1);
            float p3 = __expf(sacc[nf][3] - m1);
            sacc[nf][0] = p0; sacc[nf][1] = p1; sacc[nf][2] = p2; sacc[nf][3] = p3;
            rs0 += p0 + p1; rs1 += p2 + p3;
        }
        rs0 += __shfl_xor_sync(0xffffffffu, rs0, 1);
        rs0 += __shfl_xor_sync(0xffffffffu, rs0, 2);
        rs1 += __shfl_xor_sync(0xffffffffu, rs1, 1);
        rs1 += __shfl_xor_sync(0xffffffffu, rs1, 2);
        l0 = l0 * c0 + rs0;
        l1 = l1 * c1 + rs1;

        #pragma unroll
        for (int j = 0; j < 16; j++) {
            oacc[j][0] *= c0; oacc[j][1] *= c0;
            oacc[j][2] *= c1; oacc[j][3] *= c1;
        }

        // ---- repack P fragments (C->A layout identity), hi/lo split ----
        uint32_t ph[4][4], pl[4][4];
        #pragma unroll
        for (int kb = 0; kb < 4; kb++) {
            int f0 = 2*kb, f1 = 2*kb + 1;
            pack2_split(sacc[f0][0], sacc[f0][1], ph[kb][0], pl[kb][0]);
            pack2_split(sacc[f0][2], sacc[f0][3], ph[kb][1], pl[kb][1]);
            pack2_split(sacc[f1][0], sacc[f1][1], ph[kb][2], pl[kb][2]);
            pack2_split(sacc[f1][2], sacc[f1][3], ph[kb][3], pl[kb][3]);
        }

        // ---- O += P @ V : warp tile 16x128, 3-pass split ----
        #pragma unroll
        for (int kb = 0; kb < 4; kb++) {
            #pragma unroll
            for (int half = 0; half < 2; half++) {
                uint32_t vv[4][4], voff[4];
                #pragma unroll
                for (int n = 0; n < 4; n++) {
                    voff[n] = (uint32_t)((kb*16 + v_k) * FS2 + (half*4 + n)*16 + v_n) * 2;
                    LDM4T(vv[n], sVH + voff[n]);
                }
                #pragma unroll
                for (int j = 0; j < 8; j++)
                    mma_bf16(oacc[half*8 + j], ph[kb], &vv[j>>1][(j&1)*2]);
                #pragma unroll
                for (int j = 0; j < 8; j++)
                    mma_bf16(oacc[half*8 + j], pl[kb], &vv[j>>1][(j&1)*2]);
                #pragma unroll
                for (int n = 0; n < 4; n++) LDM4T(vv[n], sVL + voff[n]);
                #pragma unroll
                for (int j = 0; j < 8; j++)
                    mma_bf16(oacc[half*8 + j], ph[kb], &vv[j>>1][(j&1)*2]);
            }
        }
        __syncthreads();   // stage reuse fence
    }

    // ---- epilogue: normalize, split to bf16 hi/lo, store ----
    {
        float inv0 = 1.0f / l0;
        float inv1 = 1.0f / l1;
        int gr0 = q0 + wr0 + g;
        #pragma unroll
        for (int j = 0; j < 16; j++) {
            int gc = j*8 + t*2;
            uint32_t hi, lo;
            pack2_split(oacc[j][0]*inv0, oacc[j][1]*inv0, hi, lo);
            size_t o0 = ((size_t)gr0 * NH + h) * DH + gc;
            *(uint32_t*)&Oh[o0] = hi;
            *(uint32_t*)&Ol[o0] = lo;
            pack2_split(oacc[j][2]*inv1, oacc[j][3]*inv1, hi, lo);
            size_t o1 = ((size_t)(gr0 + 8) * NH + h) * DH + gc;
            *(uint32_t*)&Oh[o1] = hi;
            *(uint32_t*)&Ol[o1] = lo;
        }
    }
}

// ---------------------------------------------------------------------------
// Launch
// ---------------------------------------------------------------------------
extern "C" void kernel_launch(void* const* d_in, const int* in_sizes, int n_in,
                              void* d_out, int out_size)
{
    const float* hidden = (const float*)d_in[0];
    const float* cosb   = (const float*)d_in[1];
    const float* sinb   = (const float*)d_in[2];
    // d_in[3] = attention_mask (pure causal; applied analytically)
    const float* Wq     = (const float*)d_in[4];
    const float* Wk     = (const float*)d_in[5];
    const float* Wv     = (const float*)d_in[6];
    const float* Wo     = (const float*)d_in[7];
    float* out = (float*)d_out;

    float *qp, *kp, *vp;
    cudaGetSymbolAddress((void**)&qp, g_q);
    cudaGetSymbolAddress((void**)&kp, g_k);
    cudaGetSymbolAddress((void**)&vp, g_v);
    __nv_bfloat16 *hh, *hl, *wqh, *wql, *wkh, *wkl, *wvh, *wvl, *woh, *wol;
    __nv_bfloat16 *qh, *ql, *kh, *kl, *vh, *vl, *aoh, *aol;
    cudaGetSymbolAddress((void**)&hh,  g_hh);
    cudaGetSymbolAddress((void**)&hl,  g_hl);
    cudaGetSymbolAddress((void**)&wqh, g_wqh);
    cudaGetSymbolAddress((void**)&wql, g_wql);
    cudaGetSymbolAddress((void**)&wkh, g_wkh);
    cudaGetSymbolAddress((void**)&wkl, g_wkl);
    cudaGetSymbolAddress((void**)&wvh, g_wvh);
    cudaGetSymbolAddress((void**)&wvl, g_wvl);
    cudaGetSymbolAddress((void**)&woh, g_woh);
    cudaGetSymbolAddress((void**)&wol, g_wol);
    cudaGetSymbolAddress((void**)&qh,  g_qh);
    cudaGetSymbolAddress((void**)&ql,  g_ql);
    cudaGetSymbolAddress((void**)&kh,  g_kh);
    cudaGetSymbolAddress((void**)&kl,  g_kl);
    cudaGetSymbolAddress((void**)&vh,  g_vh);
    cudaGetSymbolAddress((void**)&vl,  g_vl);
    cudaGetSymbolAddress((void**)&aoh, g_aoh);
    cudaGetSymbolAddress((void**)&aol, g_aol);

    cudaFuncSetAttribute(flash_reg, cudaFuncAttributeMaxDynamicSharedMemorySize,
                         FLASH3_SMEM);
    cudaFuncSetAttribute(gemm_cp, cudaFuncAttributeMaxDynamicSharedMemorySize,
                         GEMM_SMEM_B);

    // Pre-split operands to bf16 hi/lo (x4 vectorized)
    split_f32<<<(SEQ*HID/4 + 255)/256, 256>>>(hidden, hh, hl, SEQ*HID/4);
    split_f32<<<(QDIM*HID/4 + 255)/256, 256>>>(Wq, wqh, wql, QDIM*HID/4);
    split_f32<<<(KVDIM*HID/4 + 255)/256, 256>>>(Wk, wkh, wkl, KVDIM*HID/4);
    split_f32<<<(KVDIM*HID/4 + 255)/256, 256>>>(Wv, wvh, wvl, KVDIM*HID/4);
    split_f32<<<(QDIM*QDIM/4 + 255)/256, 256>>>(Wo, woh, wol, QDIM*QDIM/4);

    // Q projection
    gemm_cp<<<dim3(QDIM/128, SEQ/128), 256, GEMM_SMEM_B>>>(
        hh, hl, wqh, wql, qp, wqh, wql, qp, QDIM/128, SEQ, QDIM, HID);
    // K + V projections fused into one launch
    gemm_cp<<<dim3(2*KVDIM/128, SEQ/128), 256, GEMM_SMEM_B>>>(
        hh, hl, wkh, wkl, kp, wvh, wvl, vp, KVDIM/128, SEQ, KVDIM, HID);

    // RoPE + bf16 split (Q also gets 1/sqrt(D) folded in)
    const float scale = 0.08838834764831845f;   // 128^-0.5
    rope_split<<<(SEQ*NH*32 + 255)/256, 256>>>(qp, qh, ql, cosb, sinb, NH,  scale);
    rope_split<<<(SEQ*NKV*32 + 255)/256, 256>>>(kp, kh, kl, cosb, sinb, NKV, 1.0f);
    split_f32<<<(SEQ*KVDIM/4 + 255)/256, 256>>>(vp, vh, vl, SEQ*KVDIM/4);

    // Flash attention (in-register softmax, cp.async K/V double buffer)
    flash_reg<<<dim3(SEQ/FQT, NH), 256, FLASH3_SMEM>>>(qh, ql, kh, kl, vh, vl, aoh, aol);

    // Output projection
    gemm_cp<<<dim3(QDIM/128, SEQ/128), 256, GEMM_SMEM_B>>>(
        aoh, aol, woh, wol, out, woh, wol, out, QDIM/128, SEQ, QDIM, HID);
}

// round 8
// speedup vs baseline: 3.4116x; 1.0303x over previous
#include <cuda_runtime.h>
#include <cuda_bf16.h>
#include <cstdint>
#include <math.h>

// Problem constants
#define SEQ   2048
#define HID   4096
#define NH    32
#define NKV   8
#define DH    128
#define QDIM  (NH * DH)    // 4096
#define KVDIM (NKV * DH)   // 1024

// Q scale: 1/sqrt(128) * log2(e)  (log2e folded so flash can use exp2f)
#define SCALE_Q ((float)(0.08838834764831845 * 1.4426950408889634))

// Scratch (device globals; allocation is forbidden)
__device__ __nv_bfloat16 g_hh [SEQ * HID];
__device__ __nv_bfloat16 g_hl [SEQ * HID];
__device__ __nv_bfloat16 g_wqh[QDIM * HID];
__device__ __nv_bfloat16 g_wql[QDIM * HID];
__device__ __nv_bfloat16 g_wkh[KVDIM * HID];
__device__ __nv_bfloat16 g_wkl[KVDIM * HID];
__device__ __nv_bfloat16 g_wvh[KVDIM * HID];
__device__ __nv_bfloat16 g_wvl[KVDIM * HID];
__device__ __nv_bfloat16 g_woh[QDIM * QDIM];
__device__ __nv_bfloat16 g_wol[QDIM * QDIM];
__device__ __nv_bfloat16 g_qh [SEQ * QDIM];
__device__ __nv_bfloat16 g_ql [SEQ * QDIM];
__device__ __nv_bfloat16 g_kh [SEQ * KVDIM];
__device__ __nv_bfloat16 g_kl [SEQ * KVDIM];
__device__ __nv_bfloat16 g_vh [SEQ * KVDIM];
__device__ __nv_bfloat16 g_vl [SEQ * KVDIM];
__device__ __nv_bfloat16 g_aoh[SEQ * QDIM];
__device__ __nv_bfloat16 g_aol[SEQ * QDIM];

// ---------------------------------------------------------------------------
// Helpers
// ---------------------------------------------------------------------------
__device__ __forceinline__ uint32_t smem_u32(const void* p) {
    uint32_t a;
    asm("{ .reg .u64 t; cvta.to.shared.u64 t, %1; cvt.u32.u64 %0, t; }"
        : "=r"(a) : "l"(p));
    return a;
}

#define LDM4(r, addr)                                                         \
    asm volatile("ldmatrix.sync.aligned.m8n8.x4.shared.b16 {%0,%1,%2,%3}, [%4];" \
                 : "=r"((r)[0]), "=r"((r)[1]), "=r"((r)[2]), "=r"((r)[3])     \
                 : "r"(addr))
#define LDM4T(r, addr)                                                        \
    asm volatile("ldmatrix.sync.aligned.m8n8.x4.trans.shared.b16 {%0,%1,%2,%3}, [%4];" \
                 : "=r"((r)[0]), "=r"((r)[1]), "=r"((r)[2]), "=r"((r)[3])     \
                 : "r"(addr))

__device__ __forceinline__ void mma_bf16(float* c, const uint32_t* a,
                                         const uint32_t* b) {
    asm volatile(
        "mma.sync.aligned.m16n8k16.row.col.f32.bf16.bf16.f32 "
        "{%0,%1,%2,%3}, {%4,%5,%6,%7}, {%8,%9}, {%0,%1,%2,%3};"
        : "+f"(c[0]), "+f"(c[1]), "+f"(c[2]), "+f"(c[3])
        : "r"(a[0]), "r"(a[1]), "r"(a[2]), "r"(a[3]), "r"(b[0]), "r"(b[1]));
}

__device__ __forceinline__ void cp16(uint32_t s, const void* g) {
    asm volatile("cp.async.cg.shared.global [%0], [%1], 16;"
                 :: "r"(s), "l"(g));
}
__device__ __forceinline__ void cp_commit() {
    asm volatile("cp.async.commit_group;");
}
template<int N> __device__ __forceinline__ void cp_wait() {
    asm volatile("cp.async.wait_group %0;" :: "n"(N));
}

__device__ __forceinline__ uint32_t pack_bf16x2(__nv_bfloat16 a, __nv_bfloat16 b) {
    return (uint32_t)__bfloat16_as_ushort(a) |
           ((uint32_t)__bfloat16_as_ushort(b) << 16);
}

__device__ __forceinline__ void pack2_split(float a, float b,
                                            uint32_t& hi, uint32_t& lo) {
    __nv_bfloat16 ha = __float2bfloat16(a), hb = __float2bfloat16(b);
    hi = pack_bf16x2(ha, hb);
    lo = pack_bf16x2(__float2bfloat16(a - __bfloat162float(ha)),
                     __float2bfloat16(b - __bfloat162float(hb)));
}

__device__ __forceinline__ void split1(float x, __nv_bfloat16& h, __nv_bfloat16& l) {
    h = __float2bfloat16(x);
    l = __float2bfloat16(x - __bfloat162float(h));
}

// ---------------------------------------------------------------------------
// Elementwise fp32 -> bf16 hi/lo split, ILP=4 (grid = n4/1024, n4 % 1024 == 0)
// ---------------------------------------------------------------------------
__global__ void split_f32(const float* __restrict__ X,
                          __nv_bfloat16* __restrict__ Xh,
                          __nv_bfloat16* __restrict__ Xl)
{
    int base = blockIdx.x * 1024 + threadIdx.x;
    float4 v[4];
    #pragma unroll
    for (int j = 0; j < 4; j++) v[j] = *(const float4*)(X + (size_t)(base + j*256) * 4);
    #pragma unroll
    for (int j = 0; j < 4; j++) {
        uint32_t h0, l0, h1, l1;
        pack2_split(v[j].x, v[j].y, h0, l0);
        pack2_split(v[j].z, v[j].w, h1, l1);
        size_t o = (size_t)(base + j*256) * 4;
        *(uint2*)(Xh + o) = make_uint2(h0, h1);
        *(uint2*)(Xl + o) = make_uint2(l0, l1);
    }
}

// ---------------------------------------------------------------------------
// GEMM mainloop core (shared by both GEMM kernels):
// CTA tile 128x128, BK=32, 256 threads, warp tile 64x32 (2x4 warps),
// cp.async 2-stage double buffer, bf16x3 split (AhBh + AlBh + AhBl)
// ---------------------------------------------------------------------------
#define GS 40
#define GST (128 * GS)                 // elems per half per stage
#define GSTAGE_B (4 * GST * 2)         // 40960 bytes
#define GEMM_SMEM_B (2 * GSTAGE_B)     // 81920 (also holds 128x132 fp32 staging)

struct GemmCore {
    uint32_t sb;
    int tid, wid, lid, wm2, wn2;
    int a_row, a_k, b_row, b_k;
    size_t goA[2], goB[2];
    uint32_t soB[2];
    float acc[4][4][4];

    __device__ __forceinline__ void init(uint32_t sb_, int bm, int bnl,
                                         const __nv_bfloat16* /*unused*/) {
        sb = sb_;
        tid = threadIdx.x; wid = tid >> 5; lid = tid & 31;
        wm2 = wid & 1; wn2 = wid >> 1;
        int mm = lid >> 3, lr = lid & 7;
        a_row = ((mm & 1) << 3) + lr;
        a_k   = (mm >> 1) << 3;
        b_row = ((mm >> 1) << 3) + lr;
        b_k   = (mm & 1) << 3;
        #pragma unroll
        for (int j = 0; j < 2; j++) {
            int f = tid + j * 256;
            int r = f >> 2, c8 = f & 3;
            goA[j] = (size_t)(bm + r) * HID + c8 * 8;
            goB[j] = (size_t)(bnl + r) * HID + c8 * 8;
            soB[j] = (uint32_t)(r * GS + c8 * 8) * 2;
        }
        #pragma unroll
        for (int mi = 0; mi < 4; mi++)
            #pragma unroll
            for (int nj = 0; nj < 4; nj++)
                #pragma unroll
                for (int e = 0; e < 4; e++) acc[mi][nj][e] = 0.f;
    }

    __device__ __forceinline__ void issue(const __nv_bfloat16* Ah, const __nv_bfloat16* Al,
                                          const __nv_bfloat16* Bh, const __nv_bfloat16* Bl,
                                          int ch, int s) {
        uint32_t st = sb + s * GSTAGE_B;
        #pragma unroll
        for (int j = 0; j < 2; j++) {
            cp16(st + 0*GST*2 + soB[j], Ah + goA[j] + ch * 32);
            cp16(st + 1*GST*2 + soB[j], Al + goA[j] + ch * 32);
            cp16(st + 2*GST*2 + soB[j], Bh + goB[j] + ch * 32);
            cp16(st + 3*GST*2 + soB[j], Bl + goB[j] + ch * 32);
        }
        cp_commit();
    }

    __device__ __forceinline__ void mainloop(const __nv_bfloat16* Ah, const __nv_bfloat16* Al,
                                             const __nv_bfloat16* Bh, const __nv_bfloat16* Bl) {
        const int NCH = HID / 32;
        issue(Ah, Al, Bh, Bl, 0, 0);
        for (int ch = 0; ch < NCH; ch++) {
            const int s = ch & 1;
            if (ch + 1 < NCH) { issue(Ah, Al, Bh, Bl, ch + 1, s ^ 1); cp_wait<1>(); }
            else              { cp_wait<0>(); }
            __syncthreads();

            const uint32_t sAh = sb + s * GSTAGE_B;
            const uint32_t sAl = sAh + GST * 2;
            const uint32_t sBh = sAh + 2 * GST * 2;
            const uint32_t sBl = sAh + 3 * GST * 2;

            #pragma unroll
            for (int kk = 0; kk < 32; kk += 16) {
                uint32_t ah[4][4], al[4][4], bb[2][4];
                uint32_t boff[2];
                #pragma unroll
                for (int mi = 0; mi < 4; mi++) {
                    uint32_t off = ((wm2*64 + mi*16 + a_row) * GS + kk + a_k) * 2;
                    LDM4(ah[mi], sAh + off);
                    LDM4(al[mi], sAl + off);
                }
                #pragma unroll
                for (int nt = 0; nt < 2; nt++) {
                    boff[nt] = ((wn2*32 + nt*16 + b_row) * GS + kk + b_k) * 2;
                    LDM4(bb[nt], sBh + boff[nt]);
                }
                #pragma unroll
                for (int mi = 0; mi < 4; mi++)
                    #pragma unroll
                    for (int nj = 0; nj < 4; nj++)
                        mma_bf16(acc[mi][nj], ah[mi], &bb[nj>>1][(nj&1)*2]);
                #pragma unroll
                for (int mi = 0; mi < 4; mi++)
                    #pragma unroll
                    for (int nj = 0; nj < 4; nj++)
                        mma_bf16(acc[mi][nj], al[mi], &bb[nj>>1][(nj&1)*2]);
                #pragma unroll
                for (int nt = 0; nt < 2; nt++) LDM4(bb[nt], sBl + boff[nt]);
                #pragma unroll
                for (int mi = 0; mi < 4; mi++)
                    #pragma unroll
                    for (int nj = 0; nj < 4; nj++)
                        mma_bf16(acc[mi][nj], ah[mi], &bb[nj>>1][(nj&1)*2]);
            }
            __syncthreads();
        }
    }
};

// ---------------------------------------------------------------------------
// Fused QKV projection: GEMM + rope (Q,K) / plain (V) + bf16 hi/lo split.
// Grid x: [0,32) Q, [32,40) K, [40,48) V; grid y: seq/128.
// ---------------------------------------------------------------------------
__global__ __launch_bounds__(256, 2) void gemm_qkv(
    const __nv_bfloat16* __restrict__ Ah, const __nv_bfloat16* __restrict__ Al,
    const __nv_bfloat16* __restrict__ WQh, const __nv_bfloat16* __restrict__ WQl,
    const __nv_bfloat16* __restrict__ WKh, const __nv_bfloat16* __restrict__ WKl,
    const __nv_bfloat16* __restrict__ WVh, const __nv_bfloat16* __restrict__ WVl,
    __nv_bfloat16* __restrict__ Qh, __nv_bfloat16* __restrict__ Ql,
    __nv_bfloat16* __restrict__ Kh, __nv_bfloat16* __restrict__ Kl,
    __nv_bfloat16* __restrict__ Vh, __nv_bfloat16* __restrict__ Vl,
    const float* __restrict__ cosb, const float* __restrict__ sinb)
{
    extern __shared__ __align__(16) uint16_t dsm[];
    const uint32_t sb = smem_u32(dsm);
    const int bm = blockIdx.y * 128;
    int bx = blockIdx.x;

    const __nv_bfloat16 *Bh, *Bl;
    __nv_bfloat16 *Oh, *Ol;
    int Nsec, bxl, do_rope;
    float scale;
    if (bx < 32) {
        Bh = WQh; Bl = WQl; Oh = Qh; Ol = Ql;
        Nsec = QDIM; bxl = bx; do_rope = 1; scale = SCALE_Q;
    } else if (bx < 40) {
        Bh = WKh; Bl = WKl; Oh = Kh; Ol = Kl;
        Nsec = KVDIM; bxl = bx - 32; do_rope = 1; scale = 1.0f;
    } else {
        Bh = WVh; Bl = WVl; Oh = Vh; Ol = Vl;
        Nsec = KVDIM; bxl = bx - 40; do_rope = 0; scale = 1.0f;
    }

    GemmCore core;
    core.init(sb, bm, bxl * 128, nullptr);
    core.mainloop(Ah, Al, Bh, Bl);

    // Stage fp32 tile in smem (128 x 132)
    float* st = (float*)dsm;
    const int g = core.lid >> 2, t = core.lid & 3;
    #pragma unroll
    for (int mi = 0; mi < 4; mi++)
        #pragma unroll
        for (int nj = 0; nj < 4; nj++) {
            int r = core.wm2*64 + mi*16 + g;
            int c = core.wn2*32 + nj*8 + t*2;
            *(float2*)&st[r*132 + c]     = make_float2(core.acc[mi][nj][0], core.acc[mi][nj][1]);
            *(float2*)&st[(r+8)*132 + c] = make_float2(core.acc[mi][nj][2], core.acc[mi][nj][3]);
        }
    __syncthreads();

    // Epilogue: rope/split and store
    const int tid = core.tid;
    #pragma unroll 4
    for (int it = 0; it < 32; it++) {
        int idx = tid + it * 256;
        int r = idx >> 6, d = idx & 63;
        float x0 = st[r*132 + d];
        float x1 = st[r*132 + d + 64];
        int s = bm + r;
        float y0, y1;
        if (do_rope) {
            float c  = cosb[s*128 + d];
            float sn = sinb[s*128 + d];
            y0 = (x0 * c - x1 * sn) * scale;
            y1 = (x1 * c + x0 * sn) * scale;
        } else {
            y0 = x0; y1 = x1;
        }
        size_t off = (size_t)s * Nsec + bxl * 128 + d;
        __nv_bfloat16 h, l;
        split1(y0, h, l); Oh[off] = h;      Ol[off] = l;
        split1(y1, h, l); Oh[off + 64] = h; Ol[off + 64] = l;
    }
}

// ---------------------------------------------------------------------------
// Output projection GEMM: plain fp32 output
// ---------------------------------------------------------------------------
__global__ __launch_bounds__(256, 2) void gemm_out(
    const __nv_bfloat16* __restrict__ Ah, const __nv_bfloat16* __restrict__ Al,
    const __nv_bfloat16* __restrict__ Bh, const __nv_bfloat16* __restrict__ Bl,
    float* __restrict__ C)
{
    extern __shared__ __align__(16) uint16_t dsm[];
    const uint32_t sb = smem_u32(dsm);
    const int bm = blockIdx.y * 128;
    const int bn = blockIdx.x * 128;

    GemmCore core;
    core.init(sb, bm, bn, nullptr);
    core.mainloop(Ah, Al, Bh, Bl);

    const int g = core.lid >> 2, t = core.lid & 3;
    #pragma unroll
    for (int mi = 0; mi < 4; mi++)
        #pragma unroll
        for (int nj = 0; nj < 4; nj++) {
            int r = bm + core.wm2*64 + mi*16 + g;
            int c = bn + core.wn2*32 + nj*8 + t*2;
            *(float2*)&C[(size_t)r * QDIM + c]     = make_float2(core.acc[mi][nj][0], core.acc[mi][nj][1]);
            *(float2*)&C[(size_t)(r+8) * QDIM + c] = make_float2(core.acc[mi][nj][2], core.acc[mi][nj][3]);
        }
}

// ---------------------------------------------------------------------------
// Flash attention: in-register softmax (base-2: Q pre-scaled by log2e/sqrt(D)),
// cp.async 2-stage K/V double buffer. CTA: 128 q-rows x one head, 256 threads.
// Causal, GQA (kv head = qhead>>2). Output pre-split bf16 hi/lo.
// ---------------------------------------------------------------------------
#define FQT 128
#define FKT 64
#define FS2 136
#define FQ_BYTES  (FQT * FS2 * 2)
#define FKV_ARR   (FKT * FS2 * 2)
#define FKV_STAGE (4 * FKV_ARR)
#define FOFF_QH 0
#define FOFF_QL FQ_BYTES
#define FOFF_KV (2 * FQ_BYTES)
#define FLASH3_SMEM (FOFF_KV + 2 * FKV_STAGE)   // 208896

__global__ __launch_bounds__(256, 1) void flash_reg(
    const __nv_bfloat16* __restrict__ Qh, const __nv_bfloat16* __restrict__ Ql,
    const __nv_bfloat16* __restrict__ Kh, const __nv_bfloat16* __restrict__ Kl,
    const __nv_bfloat16* __restrict__ Vh, const __nv_bfloat16* __restrict__ Vl,
    __nv_bfloat16* __restrict__ Oh, __nv_bfloat16* __restrict__ Ol)
{
    extern __shared__ char fsm[];
    const uint32_t sb = smem_u32(fsm);
    __nv_bfloat16* sQh = (__nv_bfloat16*)(fsm + FOFF_QH);
    __nv_bfloat16* sQl = (__nv_bfloat16*)(fsm + FOFF_QL);

    const int tid = threadIdx.x;
    const int wid = tid >> 5;
    const int lid = tid & 31;
    const int g   = lid >> 2;
    const int t   = lid & 3;
    const int qb  = gridDim.x - 1 - blockIdx.x;
    const int h   = blockIdx.y;
    const int kvh = h >> 2;
    const int q0  = qb * FQT;
    const int wr0 = wid * 16;

    const int mm = lid >> 3, lr = lid & 7;
    const int a_row = ((mm & 1) << 3) + lr;
    const int a_k   = (mm >> 1) << 3;
    const int b_row = ((mm >> 1) << 3) + lr;
    const int b_k   = (mm & 1) << 3;
    const int v_k   = ((mm & 1) << 3) + lr;
    const int v_n   = (mm >> 1) << 3;

    const int ntiles = 2 * qb + 2;

    auto issue_kv = [&](int kt, int s) {
        uint32_t st = sb + FOFF_KV + s * FKV_STAGE;
        const int k0 = kt * FKT;
        for (int i = tid; i < FKT * 16; i += 256) {
            int r = i >> 4, c8 = i & 15;
            size_t gb = ((size_t)(k0 + r) * NKV + kvh) * DH + c8 * 8;
            uint32_t so = (uint32_t)(r * FS2 + c8 * 8) * 2;
            cp16(st + 0*FKV_ARR + so, Kh + gb);
            cp16(st + 1*FKV_ARR + so, Kl + gb);
            cp16(st + 2*FKV_ARR + so, Vh + gb);
            cp16(st + 3*FKV_ARR + so, Vl + gb);
        }
        cp_commit();
    };

    issue_kv(0, 0);

    for (int i = tid; i < FQT * 16; i += 256) {
        int r = i >> 4, c8 = i & 15;
        size_t gb = ((size_t)(q0 + r) * NH + h) * DH + c8 * 8;
        *(uint4*)(sQh + r * FS2 + c8 * 8) = *(const uint4*)(Qh + gb);
        *(uint4*)(sQl + r * FS2 + c8 * 8) = *(const uint4*)(Ql + gb);
    }

    float m0 = -1e30f, m1 = -1e30f, l0 = 0.f, l1 = 0.f;
    float oacc[16][4];
    #pragma unroll
    for (int j = 0; j < 16; j++)
        #pragma unroll
        for (int e = 0; e < 4; e++) oacc[j][e] = 0.f;

    for (int kt = 0; kt < ntiles; kt++) {
        const int s = kt & 1;
        if (kt + 1 < ntiles) { issue_kv(kt + 1, s ^ 1); cp_wait<1>(); }
        else                 { cp_wait<0>(); }
        __syncthreads();

        const uint32_t sKH = sb + FOFF_KV + s * FKV_STAGE;
        const uint32_t sKL = sKH + FKV_ARR;
        const uint32_t sVH = sKH + 2 * FKV_ARR;
        const uint32_t sVL = sKH + 3 * FKV_ARR;
        const int k0 = kt * FKT;

        float sacc[8][4];
        #pragma unroll
        for (int j = 0; j < 8; j++)
            #pragma unroll
            for (int e = 0; e < 4; e++) sacc[j][e] = 0.f;

        #pragma unroll
        for (int kk = 0; kk < 8; kk++) {
            uint32_t qh_[4], ql_[4], kf[4][4];
            uint32_t boff[4];
            uint32_t aoff = (uint32_t)((wr0 + a_row) * FS2 + kk*16 + a_k) * 2;
            LDM4(qh_, sb + FOFF_QH + aoff);
            LDM4(ql_, sb + FOFF_QL + aoff);
            #pragma unroll
            for (int n = 0; n < 4; n++) {
                boff[n] = (uint32_t)((n*16 + b_row) * FS2 + kk*16 + b_k) * 2;
                LDM4(kf[n], sKH + boff[n]);
            }
            #pragma unroll
            for (int nf = 0; nf < 8; nf++) mma_bf16(sacc[nf], qh_, &kf[nf>>1][(nf&1)*2]);
            #pragma unroll
            for (int nf = 0; nf < 8; nf++) mma_bf16(sacc[nf], ql_, &kf[nf>>1][(nf&1)*2]);
            #pragma unroll
            for (int n = 0; n < 4; n++) LDM4(kf[n], sKL + boff[n]);
            #pragma unroll
            for (int nf = 0; nf < 8; nf++) mma_bf16(sacc[nf], qh_, &kf[nf>>1][(nf&1)*2]);
        }

        if (kt >= 2 * qb) {
            int row0 = q0 + wr0 + g;
            #pragma unroll
            for (int nf = 0; nf < 8; nf++) {
                int col = k0 + nf*8 + t*2;
                if (col     > row0)     sacc[nf][0] = -1e30f;
                if (col + 1 > row0)     sacc[nf][1] = -1e30f;
                if (col     > row0 + 8) sacc[nf][2] = -1e30f;
                if (col + 1 > row0 + 8) sacc[nf][3] = -1e30f;
            }
        }

        float tm0 = -1e30f, tm1 = -1e30f;
        #pragma unroll
        for (int nf = 0; nf < 8; nf++) {
            tm0 = fmaxf(tm0, fmaxf(sacc[nf][0], sacc[nf][1]));
            tm1 = fmaxf(tm1, fmaxf(sacc[nf][2], sacc[nf][3]));
        }
        tm0 = fmaxf(tm0, __shfl_xor_sync(0xffffffffu, tm0, 1));
        tm0 = fmaxf(tm0, __shfl_xor_sync(0xffffffffu, tm0, 2));
        tm1 = fmaxf(tm1, __shfl_xor_sync(0xffffffffu, tm1, 1));
        tm1 = fmaxf(tm1, __shfl_xor_sync(0xffffffffu, tm1, 2));
        float nm0 = fmaxf(m0, tm0), nm1 = fmaxf(m1, tm1);
        float c0 = exp2f(m0 - nm0), c1 = exp2f(m1 - nm1);
        m0 = nm0; m1 = nm1;

        float rs0 = 0.f, rs1 = 0.f;
        #pragma unroll
        for (int nf = 0; nf < 8; nf++) {
            float p0 = exp2f(sacc[nf][0] - m0);
            float p1 = exp2f(sacc[nf][1] - m0);
            float p2 = exp2f(sacc[nf][2] - m1);
            float p3 = exp2f(sacc[nf][3] - m1);
            sacc[nf][0] = p0; sacc[nf][1] = p1; sacc[nf][2] = p2; sacc[nf][3] = p3;
            rs0 += p0 + p1; rs1 += p2 + p3;
        }
        rs0 += __shfl_xor_sync(0xffffffffu, rs0, 1);
        rs0 += __shfl_xor_sync(0xffffffffu, rs0, 2);
        rs1 += __shfl_xor_sync(0xffffffffu, rs1, 1);
        rs1 += __shfl_xor_sync(0xffffffffu, rs1, 2);
        l0 = l0 * c0 + rs0;
        l1 = l1 * c1 + rs1;

        #pragma unroll
        for (int j = 0; j < 16; j++) {
            oacc[j][0] *= c0; oacc[j][1] *= c0;
            oacc[j][2] *= c1; oacc[j][3] *= c1;
        }

        uint32_t ph[4][4], pl[4][4];
        #pragma unroll
        for (int kb = 0; kb < 4; kb++) {
            int f0 = 2*kb, f1 = 2*kb + 1;
            pack2_split(sacc[f0][0], sacc[f0][1], ph[kb][0], pl[kb][0]);
            pack2_split(sacc[f0][2], sacc[f0][3], ph[kb][1], pl[kb][1]);
            pack2_split(sacc[f1][0], sacc[f1][1], ph[kb][2], pl[kb][2]);
            pack2_split(sacc[f1][2], sacc[f1][3], ph[kb][3], pl[kb][3]);
        }

        #pragma unroll
        for (int kb = 0; kb < 4; kb++) {
            #pragma unroll
            for (int half = 0; half < 2; half++) {
                uint32_t vv[4][4], voff[4];
                #pragma unroll
                for (int n = 0; n < 4; n++) {
                    voff[n] = (uint32_t)((kb*16 + v_k) * FS2 + (half*4 + n)*16 + v_n) * 2;
                    LDM4T(vv[n], sVH + voff[n]);
                }
                #pragma unroll
                for (int j = 0; j < 8; j++)
                    mma_bf16(oacc[half*8 + j], ph[kb], &vv[j>>1][(j&1)*2]);
                #pragma unroll
                for (int j = 0; j < 8; j++)
                    mma_bf16(oacc[half*8 + j], pl[kb], &vv[j>>1][(j&1)*2]);
                #pragma unroll
                for (int n = 0; n < 4; n++) LDM4T(vv[n], sVL + voff[n]);
                #pragma unroll
                for (int j = 0; j < 8; j++)
                    mma_bf16(oacc[half*8 + j], ph[kb], &vv[j>>1][(j&1)*2]);
            }
        }
        __syncthreads();
    }

    {
        float inv0 = 1.0f / l0;
        float inv1 = 1.0f / l1;
        int gr0 = q0 + wr0 + g;
        #pragma unroll
        for (int j = 0; j < 16; j++) {
            int gc = j*8 + t*2;
            uint32_t hi, lo;
            pack2_split(oacc[j][0]*inv0, oacc[j][1]*inv0, hi, lo);
            size_t o0 = ((size_t)gr0 * NH + h) * DH + gc;
            *(uint32_t*)&Oh[o0] = hi;
            *(uint32_t*)&Ol[o0] = lo;
            pack2_split(oacc[j][2]*inv1, oacc[j][3]*inv1, hi, lo);
            size_t o1 = ((size_t)(gr0 + 8) * NH + h) * DH + gc;
            *(uint32_t*)&Oh[o1] = hi;
            *(uint32_t*)&Ol[o1] = lo;
        }
    }
}

// ---------------------------------------------------------------------------
// Launch
// ---------------------------------------------------------------------------
extern "C" void kernel_launch(void* const* d_in, const int* in_sizes, int n_in,
                              void* d_out, int out_size)
{
    const float* hidden = (const float*)d_in[0];
    const float* cosb   = (const float*)d_in[1];
    const float* sinb   = (const float*)d_in[2];
    // d_in[3] = attention_mask (pure causal; applied analytically)
    const float* Wq     = (const float*)d_in[4];
    const float* Wk     = (const float*)d_in[5];
    const float* Wv     = (const float*)d_in[6];
    const float* Wo     = (const float*)d_in[7];
    float* out = (float*)d_out;

    __nv_bfloat16 *hh, *hl, *wqh, *wql, *wkh, *wkl, *wvh, *wvl, *woh, *wol;
    __nv_bfloat16 *qh, *ql, *kh, *kl, *vh, *vl, *aoh, *aol;
    cudaGetSymbolAddress((void**)&hh,  g_hh);
    cudaGetSymbolAddress((void**)&hl,  g_hl);
    cudaGetSymbolAddress((void**)&wqh, g_wqh);
    cudaGetSymbolAddress((void**)&wql, g_wql);
    cudaGetSymbolAddress((void**)&wkh, g_wkh);
    cudaGetSymbolAddress((void**)&wkl, g_wkl);
    cudaGetSymbolAddress((void**)&wvh, g_wvh);
    cudaGetSymbolAddress((void**)&wvl, g_wvl);
    cudaGetSymbolAddress((void**)&woh, g_woh);
    cudaGetSymbolAddress((void**)&wol, g_wol);
    cudaGetSymbolAddress((void**)&qh,  g_qh);
    cudaGetSymbolAddress((void**)&ql,  g_ql);
    cudaGetSymbolAddress((void**)&kh,  g_kh);
    cudaGetSymbolAddress((void**)&kl,  g_kl);
    cudaGetSymbolAddress((void**)&vh,  g_vh);
    cudaGetSymbolAddress((void**)&vl,  g_vl);
    cudaGetSymbolAddress((void**)&aoh, g_aoh);
    cudaGetSymbolAddress((void**)&aol, g_aol);

    cudaFuncSetAttribute(flash_reg, cudaFuncAttributeMaxDynamicSharedMemorySize,
                         FLASH3_SMEM);
    cudaFuncSetAttribute(gemm_qkv, cudaFuncAttributeMaxDynamicSharedMemorySize,
                         GEMM_SMEM_B);
    cudaFuncSetAttribute(gemm_out, cudaFuncAttributeMaxDynamicSharedMemorySize,
                         GEMM_SMEM_B);

    // Pre-split operands to bf16 hi/lo (ILP=4; sizes are multiples of 4096 floats)
    split_f32<<<SEQ*HID/4096, 256>>>(hidden, hh, hl);
    split_f32<<<QDIM*HID/4096, 256>>>(Wq, wqh, wql);
    split_f32<<<KVDIM*HID/4096, 256>>>(Wk, wkh, wkl);
    split_f32<<<KVDIM*HID/4096, 256>>>(Wv, wvh, wvl);
    split_f32<<<QDIM*QDIM/4096, 256>>>(Wo, woh, wol);

    // Fused QKV projection + rope + split (Q scaled by log2e/sqrt(D))
    gemm_qkv<<<dim3(48, SEQ/128), 256, GEMM_SMEM_B>>>(
        hh, hl, wqh, wql, wkh, wkl, wvh, wvl,
        qh, ql, kh, kl, vh, vl, cosb, sinb);

    // Flash attention (base-2 softmax, cp.async K/V double buffer)
    flash_reg<<<dim3(SEQ/FQT, NH), 256, FLASH3_SMEM>>>(qh, ql, kh, kl, vh, vl, aoh, aol);

    // Output projection
    gemm_out<<<dim3(QDIM/128, SEQ/128), 256, GEMM_SMEM_B>>>(aoh, aol, woh, wol, out);
}